// round 12
// baseline (speedup 1.0000x reference)
#include <cuda_runtime.h>
#include <cuda_fp16.h>
#include <math.h>
#include <stdint.h>

// ---------------------------------------------------------------------------
// CompletionNet via warp-level fp16 mma.sync (m16n8k16, fp32 accum).
// R12 = R11 with the index-ring rotation bug fixed (slots 0/1 refilled with
// offsets 4/5 after priming). Pre-transposed index quads (no shfl, linear
// broadcast int4 loads, ring depth 4) + W staged in shared memory.
// M=32 warp tile, distance-2 register gather pipeline.
// Layers 1-2 produce permuted fp16; layer 3 produces fp32.
// ---------------------------------------------------------------------------

#define NMAX  500000
#define NGMAX ((NMAX + 31) / 32)
#define EPS   1e-5f

__device__ __half g_hA[NMAX * 32];
__device__ __half g_hB[NMAX * 32];
__device__ float  g_F[NMAX * 32];
__device__ float  g_stats[3 * 64];
__device__ float4 g_Wp[62 * 128];
__device__ int4   g_nT3[27 * NGMAX * 8];   // transposed nmap3 quads
__device__ int4   g_nT2[ 8 * NGMAX * 8];   // transposed nmap2 quads

typedef unsigned int u32;

__device__ __forceinline__ u32 pack_h2(float lo, float hi) {
    u32 r; asm("cvt.rn.f16x2.f32 %0, %1, %2;" : "=r"(r) : "f"(hi), "f"(lo)); return r;
}

#define MMA_F16(d, a0, a1, a2, a3, b0, b1)                                      \
    asm volatile("mma.sync.aligned.m16n8k16.row.col.f32.f16.f16.f32 "           \
                 "{%0,%1,%2,%3}, {%4,%5,%6,%7}, {%8,%9}, {%0,%1,%2,%3};"        \
                 : "+f"(d[0]), "+f"(d[1]), "+f"(d[2]), "+f"(d[3])               \
                 : "r"(a0), "r"(a1), "r"(a2), "r"(a3), "r"(b0), "r"(b1))

// ---------------------------------------------------------------------------
__global__ void prep_weights(const float* __restrict__ W, float4* __restrict__ dst) {
    int k = blockIdx.x;
    int t = threadIdx.x;                 // 0..127
    int lane = t & 31, ntp = (t >> 5) & 1, kc = t >> 6;
    int r  = lane >> 2;
    int cL = (lane & 3) * 2;
    int co0 = (2 * ntp) * 8 + r;
    int co1 = co0 + 8;
    const float* Wk = W + k * 1024 + kc * 16 * 32;
    u32 p0 = pack_h2(Wk[(cL + 0) * 32 + co0], Wk[(cL + 1) * 32 + co0]);
    u32 p1 = pack_h2(Wk[(cL + 8) * 32 + co0], Wk[(cL + 9) * 32 + co0]);
    u32 p2 = pack_h2(Wk[(cL + 0) * 32 + co1], Wk[(cL + 1) * 32 + co1]);
    u32 p3 = pack_h2(Wk[(cL + 8) * 32 + co1], Wk[(cL + 9) * 32 + co1]);
    float4 v;
    v.x = __uint_as_float(p0); v.y = __uint_as_float(p1);
    v.z = __uint_as_float(p2); v.w = __uint_as_float(p3);
    dst[k * 128 + kc * 64 + ntp * 32 + lane] = v;
}

// ---------------------------------------------------------------------------
// nmap -> per-(k, group, gid) int4 quads {idx[gid], +8, +16, +24}
// ---------------------------------------------------------------------------
__global__ __launch_bounds__(256)
void prep_nmapT(const int* __restrict__ nmap, int4* __restrict__ dst,
                int kvol, int N, int ngroups)
{
    int i = blockIdx.x * blockDim.x + threadIdx.x;
    int total = kvol * ngroups * 8;
    if (i >= total) return;
    int gid = i & 7;
    int g   = (i >> 3) % ngroups;
    int k   = i / (ngroups * 8);
    int row = g * 32 + gid;
    const int* src = nmap + (size_t)k * N;
    int4 v;
    v.x = (row      < N) ? __ldg(src + row)      : -1;
    v.y = (row + 8  < N) ? __ldg(src + row + 8)  : -1;
    v.z = (row + 16 < N) ? __ldg(src + row + 16) : -1;
    v.w = (row + 24 < N) ? __ldg(src + row + 24) : -1;
    dst[i] = v;
}

// ---------------------------------------------------------------------------
__global__ __launch_bounds__(256)
void cvt_half_kernel(const float* __restrict__ x, __half* __restrict__ y, int N)
{
    int i = blockIdx.x * blockDim.x + threadIdx.x;
    int row = i >> 2, tg = i & 3;
    if (row >= N) return;
    const float2* src = (const float2*)(x + (size_t)row * 32);
    float2 v0 = __ldg(src + tg);
    float2 v1 = __ldg(src + tg + 4);
    float2 v2 = __ldg(src + tg + 8);
    float2 v3 = __ldg(src + tg + 12);
    uint4 o;
    o.x = pack_h2(v0.x, v0.y);
    o.y = pack_h2(v1.x, v1.y);
    o.z = pack_h2(v2.x, v2.y);
    o.w = pack_h2(v3.x, v3.y);
    ((uint4*)y)[(size_t)row * 4 + tg] = o;
}

// ---------------------------------------------------------------------------
__device__ __forceinline__ void gather4(uint4& a, uint4& b, uint4& c, uint4& d,
                                        const __half* __restrict__ in,
                                        int4 iq, int tg)
{
    a = make_uint4(0u, 0u, 0u, 0u); b = a; c = a; d = a;
    if (iq.x >= 0) a = __ldg((const uint4*)(in + (size_t)iq.x * 32) + tg);
    if (iq.y >= 0) b = __ldg((const uint4*)(in + (size_t)iq.y * 32) + tg);
    if (iq.z >= 0) c = __ldg((const uint4*)(in + (size_t)iq.z * 32) + tg);
    if (iq.w >= 0) d = __ldg((const uint4*)(in + (size_t)iq.w * 32) + tg);
}

// ---------------------------------------------------------------------------
// conv: block = 256 threads (8 warps), tile = 256 voxels x 32 out-channels.
// W staged in dynamic smem; index quads via nmapT (ring depth 4).
// Ring invariant entering iteration k: slots hold offsets {k+2..k+5}.
// ---------------------------------------------------------------------------
template<int KVOL, bool OUT_HALF>
__global__ __launch_bounds__(256, 2)
void conv_mma(const __half* __restrict__ in, const int4* __restrict__ nmapT,
              const float4* __restrict__ Wp, void* __restrict__ out_v,
              float* __restrict__ stats, int N, int ngroups)
{
    extern __shared__ float4 Wsm[];        // KVOL * 128 float4
    __shared__ float Red[8 * 64];

    const int tid  = threadIdx.x;
    const int wid  = tid >> 5, lane = tid & 31;
    const int gid  = lane >> 2, tg = lane & 3;
    const int mbase = blockIdx.x * 256;
    const int g     = blockIdx.x * 8 + wid;
    const bool gv   = (g < ngroups);

    // stage W into smem
    for (int i = tid; i < KVOL * 128; i += 256)
        Wsm[i] = __ldg(Wp + i);
    __syncthreads();

    float acc[2][4][4];
#pragma unroll
    for (int mt = 0; mt < 2; ++mt)
#pragma unroll
        for (int nt = 0; nt < 4; ++nt)
#pragma unroll
            for (int j = 0; j < 4; ++j) acc[mt][nt][j] = 0.f;

    const int4 neg1 = make_int4(-1, -1, -1, -1);
    const int4* nq = nmapT + (size_t)g * 8 + gid;
    const size_t step = (size_t)ngroups * 8;

    // ---- index-quad ring, depth 4: prime with offsets 0..3 ----
    int4 iq[4];
#pragma unroll
    for (int j = 0; j < 4; ++j)
        iq[j] = (j < KVOL && gv) ? __ldg(nq + (size_t)j * step) : neg1;

    // ---- prime 2 gather stages (consumes ring offsets 0 and 1) ----
    uint4 cA, cB, cC, cD;
    gather4(cA, cB, cC, cD, in, iq[0], tg);
    uint4 nA = make_uint4(0,0,0,0), nB = nA, nC = nA, nD = nA;
    if (KVOL > 1) gather4(nA, nB, nC, nD, in, iq[1], tg);

    // ---- refill consumed slots with offsets 4 and 5 (R11 bug fix) ----
    iq[0] = (4 < KVOL && gv) ? __ldg(nq + (size_t)4 * step) : neg1;
    iq[1] = (5 < KVOL && gv) ? __ldg(nq + (size_t)5 * step) : neg1;

#pragma unroll
    for (int k = 0; k < KVOL; ++k) {
        // gather k+2 from ring slot, then refill slot with k+6's quad
        uint4 pA = make_uint4(0,0,0,0), pB = pA, pC = pA, pD = pA;
        if (k + 2 < KVOL) gather4(pA, pB, pC, pD, in, iq[(k + 2) & 3], tg);
        iq[(k + 2) & 3] = (k + 6 < KVOL && gv)
                        ? __ldg(nq + (size_t)(k + 6) * step) : neg1;

        const float4* wk = Wsm + k * 128 + lane;
#pragma unroll
        for (int ntp = 0; ntp < 2; ++ntp) {
            float4 w0 = wk[ntp * 32];          // kc = 0
            float4 w1 = wk[64 + ntp * 32];     // kc = 1
            const u32 b00 = __float_as_uint(w0.x), b01 = __float_as_uint(w0.y);
            const u32 b02 = __float_as_uint(w0.z), b03 = __float_as_uint(w0.w);
            const u32 b10 = __float_as_uint(w1.x), b11 = __float_as_uint(w1.y);
            const u32 b12 = __float_as_uint(w1.z), b13 = __float_as_uint(w1.w);
            MMA_F16(acc[0][2 * ntp + 0], cA.x, cB.x, cA.y, cB.y, b00, b01);
            MMA_F16(acc[0][2 * ntp + 1], cA.x, cB.x, cA.y, cB.y, b02, b03);
            MMA_F16(acc[0][2 * ntp + 0], cA.z, cB.z, cA.w, cB.w, b10, b11);
            MMA_F16(acc[0][2 * ntp + 1], cA.z, cB.z, cA.w, cB.w, b12, b13);
            MMA_F16(acc[1][2 * ntp + 0], cC.x, cD.x, cC.y, cD.y, b00, b01);
            MMA_F16(acc[1][2 * ntp + 1], cC.x, cD.x, cC.y, cD.y, b02, b03);
            MMA_F16(acc[1][2 * ntp + 0], cC.z, cD.z, cC.w, cD.w, b10, b11);
            MMA_F16(acc[1][2 * ntp + 1], cC.z, cD.z, cC.w, cD.w, b12, b13);
        }
        cA = nA; cB = nB; cC = nC; cD = nD;
        nA = pA; nB = pB; nC = pC; nD = pD;
    }

    // ---- epilogue: store + fused BN stats ----
#pragma unroll
    for (int mt = 0; mt < 2; ++mt) {
        const int r0 = mbase + wid * 32 + mt * 16 + gid;
        const int r1 = r0 + 8;
        if (OUT_HALF) {
            __half* out = (__half*)out_v;
            uint4 o0, o1;
            o0.x = pack_h2(acc[mt][0][0], acc[mt][0][1]);
            o0.y = pack_h2(acc[mt][1][0], acc[mt][1][1]);
            o0.z = pack_h2(acc[mt][2][0], acc[mt][2][1]);
            o0.w = pack_h2(acc[mt][3][0], acc[mt][3][1]);
            o1.x = pack_h2(acc[mt][0][2], acc[mt][0][3]);
            o1.y = pack_h2(acc[mt][1][2], acc[mt][1][3]);
            o1.z = pack_h2(acc[mt][2][2], acc[mt][2][3]);
            o1.w = pack_h2(acc[mt][3][2], acc[mt][3][3]);
            if (r0 < N) ((uint4*)out)[(size_t)r0 * 4 + tg] = o0;
            if (r1 < N) ((uint4*)out)[(size_t)r1 * 4 + tg] = o1;
        } else {
            float* out = (float*)out_v;
#pragma unroll
            for (int nt = 0; nt < 4; ++nt) {
                int c = nt * 8 + tg * 2;
                if (r0 < N) *(float2*)(out + (size_t)r0 * 32 + c) =
                    make_float2(acc[mt][nt][0], acc[mt][nt][1]);
                if (r1 < N) *(float2*)(out + (size_t)r1 * 32 + c) =
                    make_float2(acc[mt][nt][2], acc[mt][nt][3]);
            }
        }
    }

    float s[4][2], q[4][2];
#pragma unroll
    for (int nt = 0; nt < 4; ++nt)
#pragma unroll
        for (int j = 0; j < 2; ++j) {
            float v0 = acc[0][nt][j], v1 = acc[0][nt][2 + j];
            float v2 = acc[1][nt][j], v3 = acc[1][nt][2 + j];
            s[nt][j] = (v0 + v1) + (v2 + v3);
            q[nt][j] = (v0 * v0 + v1 * v1) + (v2 * v2 + v3 * v3);
        }
#pragma unroll
    for (int off = 4; off < 32; off <<= 1)
#pragma unroll
        for (int nt = 0; nt < 4; ++nt)
#pragma unroll
            for (int j = 0; j < 2; ++j) {
                s[nt][j] += __shfl_xor_sync(0xffffffffu, s[nt][j], off);
                q[nt][j] += __shfl_xor_sync(0xffffffffu, q[nt][j], off);
            }
    if (lane < 4) {
#pragma unroll
        for (int nt = 0; nt < 4; ++nt)
#pragma unroll
            for (int j = 0; j < 2; ++j) {
                int c = nt * 8 + tg * 2 + j;
                Red[wid * 64 + c]      = s[nt][j];
                Red[wid * 64 + 32 + c] = q[nt][j];
            }
    }
    __syncthreads();
    if (tid < 64) {
        int plane = tid >> 5, c = tid & 31;
        float v = 0.f;
#pragma unroll
        for (int i = 0; i < 8; ++i) v += Red[i * 64 + plane * 32 + c];
        atomicAdd(stats + plane * 32 + c, v);
    }
}

// ---------------------------------------------------------------------------
__global__ __launch_bounds__(256)
void bnelu_h2h_kernel(const __half* __restrict__ x, __half* __restrict__ y,
                      const float* __restrict__ stats,
                      const float* __restrict__ gamma, const float* __restrict__ beta,
                      int N)
{
    __shared__ float sc[32], sh[32];
    if (threadIdx.x < 32) {
        int c = threadIdx.x;
        float inv  = 1.0f / (float)N;
        float mean = stats[c] * inv;
        float var  = stats[32 + c] * inv - mean * mean;
        float sfac = rsqrtf(var + EPS) * gamma[c];
        sc[c] = sfac;
        sh[c] = beta[c] - mean * sfac;
    }
    __syncthreads();

    int i = blockIdx.x * blockDim.x + threadIdx.x;
    int row = i >> 2, tg = i & 3;
    if (row >= N) return;
    uint4 v = __ldg((const uint4*)x + (size_t)row * 4 + tg);
    uint4 o;
#pragma unroll
    for (int qd = 0; qd < 4; ++qd) {
        int c = tg * 2 + qd * 8;
        __half2 h = *(__half2*)(((u32*)&v) + qd);
        float2 f = __half22float2(h);
        float z0 = f.x * sc[c] + sh[c];
        float z1 = f.y * sc[c + 1] + sh[c + 1];
        z0 = (z0 > 0.f) ? z0 : expm1f(z0);
        z1 = (z1 > 0.f) ? z1 : expm1f(z1);
        ((u32*)&o)[qd] = pack_h2(z0, z1);
    }
    ((uint4*)y)[(size_t)row * 4 + tg] = o;
}

// ---------------------------------------------------------------------------
__global__ __launch_bounds__(256)
void bnelu_f32_kernel(const float* __restrict__ x, float* __restrict__ y,
                      const float* __restrict__ stats,
                      const float* __restrict__ gamma, const float* __restrict__ beta,
                      int N)
{
    __shared__ float sc[32], sh[32];
    if (threadIdx.x < 32) {
        int c = threadIdx.x;
        float inv  = 1.0f / (float)N;
        float mean = stats[c] * inv;
        float var  = stats[32 + c] * inv - mean * mean;
        float sfac = rsqrtf(var + EPS) * gamma[c];
        sc[c] = sfac;
        sh[c] = beta[c] - mean * sfac;
    }
    __syncthreads();
    const int total4 = N * 8;
    for (int i = blockIdx.x * blockDim.x + threadIdx.x; i < total4;
         i += gridDim.x * blockDim.x) {
        float4 v = ((const float4*)x)[i];
        int c = (i * 4) & 31;
        float z;
        z = v.x * sc[c + 0] + sh[c + 0]; v.x = (z > 0.f) ? z : expm1f(z);
        z = v.y * sc[c + 1] + sh[c + 1]; v.y = (z > 0.f) ? z : expm1f(z);
        z = v.z * sc[c + 2] + sh[c + 2]; v.z = (z > 0.f) ? z : expm1f(z);
        z = v.w * sc[c + 3] + sh[c + 3]; v.w = (z > 0.f) ? z : expm1f(z);
        ((float4*)y)[i] = v;
    }
}

// ---------------------------------------------------------------------------
extern "C" void kernel_launch(void* const* d_in, const int* in_sizes, int n_in,
                              void* d_out, int out_size)
{
    const float* feats = (const float*)d_in[0];
    const float* W1    = (const float*)d_in[1];
    const float* g1    = (const float*)d_in[2];
    const float* b1    = (const float*)d_in[3];
    const float* W2    = (const float*)d_in[4];
    const float* g2    = (const float*)d_in[5];
    const float* b2    = (const float*)d_in[6];
    const float* W3    = (const float*)d_in[7];
    const float* g3    = (const float*)d_in[8];
    const float* b3    = (const float*)d_in[9];
    const int*   nmap3 = (const int*)d_in[10];
    const int*   nmap2 = (const int*)d_in[11];

    const int N = in_sizes[0] / 32;
    const int ntiles  = (N + 255) / 256;
    const int nquads  = (N * 4 + 255) / 256;
    const int ngroups = (N + 31) / 32;

    __half *hA, *hB;
    float *F, *stats;
    float4* Wp;
    int4 *nT3, *nT2;
    cudaGetSymbolAddress((void**)&hA,    g_hA);
    cudaGetSymbolAddress((void**)&hB,    g_hB);
    cudaGetSymbolAddress((void**)&F,     g_F);
    cudaGetSymbolAddress((void**)&stats, g_stats);
    cudaGetSymbolAddress((void**)&Wp,    g_Wp);
    cudaGetSymbolAddress((void**)&nT3,   g_nT3);
    cudaGetSymbolAddress((void**)&nT2,   g_nT2);

    cudaFuncSetAttribute(conv_mma<27, true>,
        cudaFuncAttributeMaxDynamicSharedMemorySize, 27 * 2048);
    cudaFuncSetAttribute(conv_mma<27, false>,
        cudaFuncAttributeMaxDynamicSharedMemorySize, 27 * 2048);
    cudaFuncSetAttribute(conv_mma<8, true>,
        cudaFuncAttributeMaxDynamicSharedMemorySize, 8 * 2048);

    cudaMemsetAsync(stats, 0, 3 * 64 * sizeof(float), 0);
    prep_weights<<<27, 128>>>(W1, Wp + 0 * 128);
    prep_weights<<< 8, 128>>>(W2, Wp + 27 * 128);
    prep_weights<<<27, 128>>>(W3, Wp + 35 * 128);
    {
        int tot3 = 27 * ngroups * 8;
        int tot2 = 8 * ngroups * 8;
        prep_nmapT<<<(tot3 + 255) / 256, 256>>>(nmap3, nT3, 27, N, ngroups);
        prep_nmapT<<<(tot2 + 255) / 256, 256>>>(nmap2, nT2, 8, N, ngroups);
    }
    cvt_half_kernel<<<nquads, 256>>>(feats, hA, N);

    conv_mma<27, true><<<ntiles, 256, 27 * 2048>>>(hA, nT3, Wp + 0 * 128, hB, stats + 0, N, ngroups);
    bnelu_h2h_kernel<<<nquads, 256>>>(hB, hB, stats + 0, g1, b1, N);

    conv_mma<8, true><<<ntiles, 256, 8 * 2048>>>(hB, nT2, Wp + 27 * 128, hA, stats + 64, N, ngroups);
    bnelu_h2h_kernel<<<nquads, 256>>>(hA, hA, stats + 64, g2, b2, N);

    conv_mma<27, false><<<ntiles, 256, 27 * 2048>>>(hA, nT3, Wp + 35 * 128, F, stats + 128, N, ngroups);
    bnelu_f32_kernel<<<2048, 256>>>(F, (float*)d_out, stats + 128, g3, b3, N);
}

// round 13
// speedup vs baseline: 1.1307x; 1.1307x over previous
#include <cuda_runtime.h>
#include <cuda_fp16.h>
#include <math.h>
#include <stdint.h>

// ---------------------------------------------------------------------------
// CompletionNet via warp-level fp16 mma.sync (m16n8k16, fp32 accum).
// R13 = R10 (best) with the gather pipeline deepened to distance 3.
// M=32 warp tile, register-direct fragment gather, idx ring depth 4
// (idx loaded 4 iterations before its shuffle).
// Layers 1-2 produce permuted fp16; layer 3 produces fp32.
// ---------------------------------------------------------------------------

#define NMAX 500000
#define EPS  1e-5f

__device__ __half g_hA[NMAX * 32];
__device__ __half g_hB[NMAX * 32];
__device__ float  g_F[NMAX * 32];
__device__ float  g_stats[3 * 64];
__device__ float4 g_Wp[62 * 128];

typedef unsigned int u32;

__device__ __forceinline__ u32 pack_h2(float lo, float hi) {
    u32 r; asm("cvt.rn.f16x2.f32 %0, %1, %2;" : "=r"(r) : "f"(hi), "f"(lo)); return r;
}

#define MMA_F16(d, a0, a1, a2, a3, b0, b1)                                      \
    asm volatile("mma.sync.aligned.m16n8k16.row.col.f32.f16.f16.f32 "           \
                 "{%0,%1,%2,%3}, {%4,%5,%6,%7}, {%8,%9}, {%0,%1,%2,%3};"        \
                 : "+f"(d[0]), "+f"(d[1]), "+f"(d[2]), "+f"(d[3])               \
                 : "r"(a0), "r"(a1), "r"(a2), "r"(a3), "r"(b0), "r"(b1))

// ---------------------------------------------------------------------------
__global__ void prep_weights(const float* __restrict__ W, float4* __restrict__ dst) {
    int k = blockIdx.x;
    int t = threadIdx.x;                 // 0..127
    int lane = t & 31, ntp = (t >> 5) & 1, kc = t >> 6;
    int r  = lane >> 2;
    int cL = (lane & 3) * 2;
    int co0 = (2 * ntp) * 8 + r;
    int co1 = co0 + 8;
    const float* Wk = W + k * 1024 + kc * 16 * 32;
    u32 p0 = pack_h2(Wk[(cL + 0) * 32 + co0], Wk[(cL + 1) * 32 + co0]);
    u32 p1 = pack_h2(Wk[(cL + 8) * 32 + co0], Wk[(cL + 9) * 32 + co0]);
    u32 p2 = pack_h2(Wk[(cL + 0) * 32 + co1], Wk[(cL + 1) * 32 + co1]);
    u32 p3 = pack_h2(Wk[(cL + 8) * 32 + co1], Wk[(cL + 9) * 32 + co1]);
    float4 v;
    v.x = __uint_as_float(p0); v.y = __uint_as_float(p1);
    v.z = __uint_as_float(p2); v.w = __uint_as_float(p3);
    dst[k * 128 + kc * 64 + ntp * 32 + lane] = v;
}

// ---------------------------------------------------------------------------
__global__ __launch_bounds__(256)
void cvt_half_kernel(const float* __restrict__ x, __half* __restrict__ y, int N)
{
    int i = blockIdx.x * blockDim.x + threadIdx.x;
    int row = i >> 2, tg = i & 3;
    if (row >= N) return;
    const float2* src = (const float2*)(x + (size_t)row * 32);
    float2 v0 = __ldg(src + tg);
    float2 v1 = __ldg(src + tg + 4);
    float2 v2 = __ldg(src + tg + 8);
    float2 v3 = __ldg(src + tg + 12);
    uint4 o;
    o.x = pack_h2(v0.x, v0.y);
    o.y = pack_h2(v1.x, v1.y);
    o.z = pack_h2(v2.x, v2.y);
    o.w = pack_h2(v3.x, v3.y);
    ((uint4*)y)[(size_t)row * 4 + tg] = o;
}

// ---------------------------------------------------------------------------
__device__ __forceinline__ void gather4(uint4& a, uint4& b, uint4& c, uint4& d,
                                        const __half* __restrict__ in,
                                        int idx, int gid, int tg)
{
    const int iA = __shfl_sync(0xffffffffu, idx, gid);
    const int iB = __shfl_sync(0xffffffffu, idx, 8 + gid);
    const int iC = __shfl_sync(0xffffffffu, idx, 16 + gid);
    const int iD = __shfl_sync(0xffffffffu, idx, 24 + gid);
    a = make_uint4(0u, 0u, 0u, 0u); b = a; c = a; d = a;
    if (iA >= 0) a = __ldg((const uint4*)(in + (size_t)iA * 32) + tg);
    if (iB >= 0) b = __ldg((const uint4*)(in + (size_t)iB * 32) + tg);
    if (iC >= 0) c = __ldg((const uint4*)(in + (size_t)iC * 32) + tg);
    if (iD >= 0) d = __ldg((const uint4*)(in + (size_t)iD * 32) + tg);
}

// ---------------------------------------------------------------------------
// conv: block = 256 threads (8 warps), tile = 256 voxels x 32 out-channels.
// Warp tile M=32. Gather distance-3 (4 live fragment sets), idx ring depth 4.
// Ring invariant entering iteration k: slots hold idx for offsets {k+3..k+6}.
// OUT_HALF: write permuted fp16 (one uint4 per row-quarter); else fp32.
// ---------------------------------------------------------------------------
template<int KVOL, bool OUT_HALF>
__global__ __launch_bounds__(256, 2)
void conv_mma(const __half* __restrict__ in, const int* __restrict__ nmap,
              const float4* __restrict__ Wp, void* __restrict__ out_v,
              float* __restrict__ stats, int N)
{
    __shared__ float Red[8 * 64];

    const int tid  = threadIdx.x;
    const int wid  = tid >> 5, lane = tid & 31;
    const int gid  = lane >> 2, tg = lane & 3;
    const int mbase = blockIdx.x * 256;
    const int mrow  = mbase + wid * 32 + lane;
    const bool mv   = (mrow < N);

    float acc[2][4][4];
#pragma unroll
    for (int mt = 0; mt < 2; ++mt)
#pragma unroll
        for (int nt = 0; nt < 4; ++nt)
#pragma unroll
            for (int j = 0; j < 4; ++j) acc[mt][nt][j] = 0.f;

    // ---- idx ring depth 4: prime with offsets 0..3 ----
    int idxr[4];
#pragma unroll
    for (int j = 0; j < 4; ++j)
        idxr[j] = (j < KVOL && mv) ? __ldg(nmap + (size_t)j * N + mrow) : -1;

    // ---- prime 3 gather stages (consumes ring offsets 0,1,2) ----
    uint4 cA, cB, cC, cD;
    gather4(cA, cB, cC, cD, in, idxr[0], gid, tg);
    uint4 n1A = make_uint4(0,0,0,0), n1B = n1A, n1C = n1A, n1D = n1A;
    if (KVOL > 1) gather4(n1A, n1B, n1C, n1D, in, idxr[1], gid, tg);
    uint4 n2A = make_uint4(0,0,0,0), n2B = n2A, n2C = n2A, n2D = n2A;
    if (KVOL > 2) gather4(n2A, n2B, n2C, n2D, in, idxr[2], gid, tg);

    // ---- refill consumed slots with offsets 4,5,6 ----
    idxr[0] = (4 < KVOL && mv) ? __ldg(nmap + (size_t)4 * N + mrow) : -1;
    idxr[1] = (5 < KVOL && mv) ? __ldg(nmap + (size_t)5 * N + mrow) : -1;
    idxr[2] = (6 < KVOL && mv) ? __ldg(nmap + (size_t)6 * N + mrow) : -1;

#pragma unroll
    for (int k = 0; k < KVOL; ++k) {
        // gather k+3 from ring slot (k+3)&3, then refill slot with k+7's idx
        uint4 pA = make_uint4(0,0,0,0), pB = pA, pC = pA, pD = pA;
        if (k + 3 < KVOL) gather4(pA, pB, pC, pD, in, idxr[(k + 3) & 3], gid, tg);
        idxr[(k + 3) & 3] = (k + 7 < KVOL && mv)
                          ? __ldg(nmap + (size_t)(k + 7) * N + mrow) : -1;

        const float4* wb = Wp + (size_t)k * 128 + lane;
#pragma unroll
        for (int ntp = 0; ntp < 2; ++ntp) {
            float4 w0 = __ldg(wb + ntp * 32);          // kc = 0
            float4 w1 = __ldg(wb + 64 + ntp * 32);     // kc = 1
            const u32 b00 = __float_as_uint(w0.x), b01 = __float_as_uint(w0.y);
            const u32 b02 = __float_as_uint(w0.z), b03 = __float_as_uint(w0.w);
            const u32 b10 = __float_as_uint(w1.x), b11 = __float_as_uint(w1.y);
            const u32 b12 = __float_as_uint(w1.z), b13 = __float_as_uint(w1.w);
            MMA_F16(acc[0][2 * ntp + 0], cA.x, cB.x, cA.y, cB.y, b00, b01);
            MMA_F16(acc[0][2 * ntp + 1], cA.x, cB.x, cA.y, cB.y, b02, b03);
            MMA_F16(acc[0][2 * ntp + 0], cA.z, cB.z, cA.w, cB.w, b10, b11);
            MMA_F16(acc[0][2 * ntp + 1], cA.z, cB.z, cA.w, cB.w, b12, b13);
            MMA_F16(acc[1][2 * ntp + 0], cC.x, cD.x, cC.y, cD.y, b00, b01);
            MMA_F16(acc[1][2 * ntp + 1], cC.x, cD.x, cC.y, cD.y, b02, b03);
            MMA_F16(acc[1][2 * ntp + 0], cC.z, cD.z, cC.w, cD.w, b10, b11);
            MMA_F16(acc[1][2 * ntp + 1], cC.z, cD.z, cC.w, cD.w, b12, b13);
        }
        cA = n1A; cB = n1B; cC = n1C; cD = n1D;
        n1A = n2A; n1B = n2B; n1C = n2C; n1D = n2D;
        n2A = pA;  n2B = pB;  n2C = pC;  n2D = pD;
    }

    // ---- epilogue: store + fused BN stats (stats from fp32 accumulators) ----
#pragma unroll
    for (int mt = 0; mt < 2; ++mt) {
        const int r0 = mbase + wid * 32 + mt * 16 + gid;
        const int r1 = r0 + 8;
        if (OUT_HALF) {
            __half* out = (__half*)out_v;
            uint4 o0, o1;
            o0.x = pack_h2(acc[mt][0][0], acc[mt][0][1]);
            o0.y = pack_h2(acc[mt][1][0], acc[mt][1][1]);
            o0.z = pack_h2(acc[mt][2][0], acc[mt][2][1]);
            o0.w = pack_h2(acc[mt][3][0], acc[mt][3][1]);
            o1.x = pack_h2(acc[mt][0][2], acc[mt][0][3]);
            o1.y = pack_h2(acc[mt][1][2], acc[mt][1][3]);
            o1.z = pack_h2(acc[mt][2][2], acc[mt][2][3]);
            o1.w = pack_h2(acc[mt][3][2], acc[mt][3][3]);
            if (r0 < N) ((uint4*)out)[(size_t)r0 * 4 + tg] = o0;
            if (r1 < N) ((uint4*)out)[(size_t)r1 * 4 + tg] = o1;
        } else {
            float* out = (float*)out_v;
#pragma unroll
            for (int nt = 0; nt < 4; ++nt) {
                int c = nt * 8 + tg * 2;
                if (r0 < N) *(float2*)(out + (size_t)r0 * 32 + c) =
                    make_float2(acc[mt][nt][0], acc[mt][nt][1]);
                if (r1 < N) *(float2*)(out + (size_t)r1 * 32 + c) =
                    make_float2(acc[mt][nt][2], acc[mt][nt][3]);
            }
        }
    }

    float s[4][2], q[4][2];
#pragma unroll
    for (int nt = 0; nt < 4; ++nt)
#pragma unroll
        for (int j = 0; j < 2; ++j) {
            float v0 = acc[0][nt][j], v1 = acc[0][nt][2 + j];
            float v2 = acc[1][nt][j], v3 = acc[1][nt][2 + j];
            s[nt][j] = (v0 + v1) + (v2 + v3);
            q[nt][j] = (v0 * v0 + v1 * v1) + (v2 * v2 + v3 * v3);
        }
#pragma unroll
    for (int off = 4; off < 32; off <<= 1)
#pragma unroll
        for (int nt = 0; nt < 4; ++nt)
#pragma unroll
            for (int j = 0; j < 2; ++j) {
                s[nt][j] += __shfl_xor_sync(0xffffffffu, s[nt][j], off);
                q[nt][j] += __shfl_xor_sync(0xffffffffu, q[nt][j], off);
            }
    if (lane < 4) {
#pragma unroll
        for (int nt = 0; nt < 4; ++nt)
#pragma unroll
            for (int j = 0; j < 2; ++j) {
                int c = nt * 8 + tg * 2 + j;
                Red[wid * 64 + c]      = s[nt][j];
                Red[wid * 64 + 32 + c] = q[nt][j];
            }
    }
    __syncthreads();
    if (tid < 64) {
        int plane = tid >> 5, c = tid & 31;
        float v = 0.f;
#pragma unroll
        for (int i = 0; i < 8; ++i) v += Red[i * 64 + plane * 32 + c];
        atomicAdd(stats + plane * 32 + c, v);
    }
}

// ---------------------------------------------------------------------------
__global__ __launch_bounds__(256)
void bnelu_h2h_kernel(const __half* __restrict__ x, __half* __restrict__ y,
                      const float* __restrict__ stats,
                      const float* __restrict__ gamma, const float* __restrict__ beta,
                      int N)
{
    __shared__ float sc[32], sh[32];
    if (threadIdx.x < 32) {
        int c = threadIdx.x;
        float inv  = 1.0f / (float)N;
        float mean = stats[c] * inv;
        float var  = stats[32 + c] * inv - mean * mean;
        float sfac = rsqrtf(var + EPS) * gamma[c];
        sc[c] = sfac;
        sh[c] = beta[c] - mean * sfac;
    }
    __syncthreads();

    int i = blockIdx.x * blockDim.x + threadIdx.x;
    int row = i >> 2, tg = i & 3;
    if (row >= N) return;
    uint4 v = __ldg((const uint4*)x + (size_t)row * 4 + tg);
    uint4 o;
#pragma unroll
    for (int qd = 0; qd < 4; ++qd) {
        int c = tg * 2 + qd * 8;
        __half2 h = *(__half2*)(((u32*)&v) + qd);
        float2 f = __half22float2(h);
        float z0 = f.x * sc[c] + sh[c];
        float z1 = f.y * sc[c + 1] + sh[c + 1];
        z0 = (z0 > 0.f) ? z0 : expm1f(z0);
        z1 = (z1 > 0.f) ? z1 : expm1f(z1);
        ((u32*)&o)[qd] = pack_h2(z0, z1);
    }
    ((uint4*)y)[(size_t)row * 4 + tg] = o;
}

// ---------------------------------------------------------------------------
__global__ __launch_bounds__(256)
void bnelu_f32_kernel(const float* __restrict__ x, float* __restrict__ y,
                      const float* __restrict__ stats,
                      const float* __restrict__ gamma, const float* __restrict__ beta,
                      int N)
{
    __shared__ float sc[32], sh[32];
    if (threadIdx.x < 32) {
        int c = threadIdx.x;
        float inv  = 1.0f / (float)N;
        float mean = stats[c] * inv;
        float var  = stats[32 + c] * inv - mean * mean;
        float sfac = rsqrtf(var + EPS) * gamma[c];
        sc[c] = sfac;
        sh[c] = beta[c] - mean * sfac;
    }
    __syncthreads();
    const int total4 = N * 8;
    for (int i = blockIdx.x * blockDim.x + threadIdx.x; i < total4;
         i += gridDim.x * blockDim.x) {
        float4 v = ((const float4*)x)[i];
        int c = (i * 4) & 31;
        float z;
        z = v.x * sc[c + 0] + sh[c + 0]; v.x = (z > 0.f) ? z : expm1f(z);
        z = v.y * sc[c + 1] + sh[c + 1]; v.y = (z > 0.f) ? z : expm1f(z);
        z = v.z * sc[c + 2] + sh[c + 2]; v.z = (z > 0.f) ? z : expm1f(z);
        z = v.w * sc[c + 3] + sh[c + 3]; v.w = (z > 0.f) ? z : expm1f(z);
        ((float4*)y)[i] = v;
    }
}

// ---------------------------------------------------------------------------
extern "C" void kernel_launch(void* const* d_in, const int* in_sizes, int n_in,
                              void* d_out, int out_size)
{
    const float* feats = (const float*)d_in[0];
    const float* W1    = (const float*)d_in[1];
    const float* g1    = (const float*)d_in[2];
    const float* b1    = (const float*)d_in[3];
    const float* W2    = (const float*)d_in[4];
    const float* g2    = (const float*)d_in[5];
    const float* b2    = (const float*)d_in[6];
    const float* W3    = (const float*)d_in[7];
    const float* g3    = (const float*)d_in[8];
    const float* b3    = (const float*)d_in[9];
    const int*   nmap3 = (const int*)d_in[10];
    const int*   nmap2 = (const int*)d_in[11];

    const int N = in_sizes[0] / 32;
    const int ntiles = (N + 255) / 256;
    const int nquads = (N * 4 + 255) / 256;

    __half *hA, *hB;
    float *F, *stats;
    float4* Wp;
    cudaGetSymbolAddress((void**)&hA,    g_hA);
    cudaGetSymbolAddress((void**)&hB,    g_hB);
    cudaGetSymbolAddress((void**)&F,     g_F);
    cudaGetSymbolAddress((void**)&stats, g_stats);
    cudaGetSymbolAddress((void**)&Wp,    g_Wp);

    cudaMemsetAsync(stats, 0, 3 * 64 * sizeof(float), 0);
    prep_weights<<<27, 128>>>(W1, Wp + 0 * 128);
    prep_weights<<< 8, 128>>>(W2, Wp + 27 * 128);
    prep_weights<<<27, 128>>>(W3, Wp + 35 * 128);
    cvt_half_kernel<<<nquads, 256>>>(feats, hA, N);

    conv_mma<27, true><<<ntiles, 256>>>(hA, nmap3, Wp + 0 * 128, hB, stats + 0, N);
    bnelu_h2h_kernel<<<nquads, 256>>>(hB, hB, stats + 0, g1, b1, N);

    conv_mma<8, true><<<ntiles, 256>>>(hB, nmap2, Wp + 27 * 128, hA, stats + 64, N);
    bnelu_h2h_kernel<<<nquads, 256>>>(hA, hA, stats + 64, g2, b2, N);

    conv_mma<27, false><<<ntiles, 256>>>(hA, nmap3, Wp + 35 * 128, F, stats + 128, N);
    bnelu_f32_kernel<<<2048, 256>>>(F, (float*)d_out, stats + 128, g3, b3, N);
}

// round 14
// speedup vs baseline: 1.1308x; 1.0001x over previous
#include <cuda_runtime.h>
#include <cuda_fp16.h>
#include <math.h>
#include <stdint.h>

// ---------------------------------------------------------------------------
// CompletionNet via warp-level fp16 mma.sync (m16n8k16, fp32 accum).
// R13 = R10 (best) with the gather pipeline deepened to distance 3.
// M=32 warp tile, register-direct fragment gather, idx ring depth 4
// (idx loaded 4 iterations before its shuffle).
// Layers 1-2 produce permuted fp16; layer 3 produces fp32.
// ---------------------------------------------------------------------------

#define NMAX 500000
#define EPS  1e-5f

__device__ __half g_hA[NMAX * 32];
__device__ __half g_hB[NMAX * 32];
__device__ float  g_F[NMAX * 32];
__device__ float  g_stats[3 * 64];
__device__ float4 g_Wp[62 * 128];

typedef unsigned int u32;

__device__ __forceinline__ u32 pack_h2(float lo, float hi) {
    u32 r; asm("cvt.rn.f16x2.f32 %0, %1, %2;" : "=r"(r) : "f"(hi), "f"(lo)); return r;
}

#define MMA_F16(d, a0, a1, a2, a3, b0, b1)                                      \
    asm volatile("mma.sync.aligned.m16n8k16.row.col.f32.f16.f16.f32 "           \
                 "{%0,%1,%2,%3}, {%4,%5,%6,%7}, {%8,%9}, {%0,%1,%2,%3};"        \
                 : "+f"(d[0]), "+f"(d[1]), "+f"(d[2]), "+f"(d[3])               \
                 : "r"(a0), "r"(a1), "r"(a2), "r"(a3), "r"(b0), "r"(b1))

// ---------------------------------------------------------------------------
__global__ void prep_weights(const float* __restrict__ W, float4* __restrict__ dst) {
    int k = blockIdx.x;
    int t = threadIdx.x;                 // 0..127
    int lane = t & 31, ntp = (t >> 5) & 1, kc = t >> 6;
    int r  = lane >> 2;
    int cL = (lane & 3) * 2;
    int co0 = (2 * ntp) * 8 + r;
    int co1 = co0 + 8;
    const float* Wk = W + k * 1024 + kc * 16 * 32;
    u32 p0 = pack_h2(Wk[(cL + 0) * 32 + co0], Wk[(cL + 1) * 32 + co0]);
    u32 p1 = pack_h2(Wk[(cL + 8) * 32 + co0], Wk[(cL + 9) * 32 + co0]);
    u32 p2 = pack_h2(Wk[(cL + 0) * 32 + co1], Wk[(cL + 1) * 32 + co1]);
    u32 p3 = pack_h2(Wk[(cL + 8) * 32 + co1], Wk[(cL + 9) * 32 + co1]);
    float4 v;
    v.x = __uint_as_float(p0); v.y = __uint_as_float(p1);
    v.z = __uint_as_float(p2); v.w = __uint_as_float(p3);
    dst[k * 128 + kc * 64 + ntp * 32 + lane] = v;
}

// ---------------------------------------------------------------------------
__global__ __launch_bounds__(256)
void cvt_half_kernel(const float* __restrict__ x, __half* __restrict__ y, int N)
{
    int i = blockIdx.x * blockDim.x + threadIdx.x;
    int row = i >> 2, tg = i & 3;
    if (row >= N) return;
    const float2* src = (const float2*)(x + (size_t)row * 32);
    float2 v0 = __ldg(src + tg);
    float2 v1 = __ldg(src + tg + 4);
    float2 v2 = __ldg(src + tg + 8);
    float2 v3 = __ldg(src + tg + 12);
    uint4 o;
    o.x = pack_h2(v0.x, v0.y);
    o.y = pack_h2(v1.x, v1.y);
    o.z = pack_h2(v2.x, v2.y);
    o.w = pack_h2(v3.x, v3.y);
    ((uint4*)y)[(size_t)row * 4 + tg] = o;
}

// ---------------------------------------------------------------------------
__device__ __forceinline__ void gather4(uint4& a, uint4& b, uint4& c, uint4& d,
                                        const __half* __restrict__ in,
                                        int idx, int gid, int tg)
{
    const int iA = __shfl_sync(0xffffffffu, idx, gid);
    const int iB = __shfl_sync(0xffffffffu, idx, 8 + gid);
    const int iC = __shfl_sync(0xffffffffu, idx, 16 + gid);
    const int iD = __shfl_sync(0xffffffffu, idx, 24 + gid);
    a = make_uint4(0u, 0u, 0u, 0u); b = a; c = a; d = a;
    if (iA >= 0) a = __ldg((const uint4*)(in + (size_t)iA * 32) + tg);
    if (iB >= 0) b = __ldg((const uint4*)(in + (size_t)iB * 32) + tg);
    if (iC >= 0) c = __ldg((const uint4*)(in + (size_t)iC * 32) + tg);
    if (iD >= 0) d = __ldg((const uint4*)(in + (size_t)iD * 32) + tg);
}

// ---------------------------------------------------------------------------
// conv: block = 256 threads (8 warps), tile = 256 voxels x 32 out-channels.
// Warp tile M=32. Gather distance-3 (4 live fragment sets), idx ring depth 4.
// Ring invariant entering iteration k: slots hold idx for offsets {k+3..k+6}.
// OUT_HALF: write permuted fp16 (one uint4 per row-quarter); else fp32.
// ---------------------------------------------------------------------------
template<int KVOL, bool OUT_HALF>
__global__ __launch_bounds__(256, 2)
void conv_mma(const __half* __restrict__ in, const int* __restrict__ nmap,
              const float4* __restrict__ Wp, void* __restrict__ out_v,
              float* __restrict__ stats, int N)
{
    __shared__ float Red[8 * 64];

    const int tid  = threadIdx.x;
    const int wid  = tid >> 5, lane = tid & 31;
    const int gid  = lane >> 2, tg = lane & 3;
    const int mbase = blockIdx.x * 256;
    const int mrow  = mbase + wid * 32 + lane;
    const bool mv   = (mrow < N);

    float acc[2][4][4];
#pragma unroll
    for (int mt = 0; mt < 2; ++mt)
#pragma unroll
        for (int nt = 0; nt < 4; ++nt)
#pragma unroll
            for (int j = 0; j < 4; ++j) acc[mt][nt][j] = 0.f;

    // ---- idx ring depth 4: prime with offsets 0..3 ----
    int idxr[4];
#pragma unroll
    for (int j = 0; j < 4; ++j)
        idxr[j] = (j < KVOL && mv) ? __ldg(nmap + (size_t)j * N + mrow) : -1;

    // ---- prime 3 gather stages (consumes ring offsets 0,1,2) ----
    uint4 cA, cB, cC, cD;
    gather4(cA, cB, cC, cD, in, idxr[0], gid, tg);
    uint4 n1A = make_uint4(0,0,0,0), n1B = n1A, n1C = n1A, n1D = n1A;
    if (KVOL > 1) gather4(n1A, n1B, n1C, n1D, in, idxr[1], gid, tg);
    uint4 n2A = make_uint4(0,0,0,0), n2B = n2A, n2C = n2A, n2D = n2A;
    if (KVOL > 2) gather4(n2A, n2B, n2C, n2D, in, idxr[2], gid, tg);

    // ---- refill consumed slots with offsets 4,5,6 ----
    idxr[0] = (4 < KVOL && mv) ? __ldg(nmap + (size_t)4 * N + mrow) : -1;
    idxr[1] = (5 < KVOL && mv) ? __ldg(nmap + (size_t)5 * N + mrow) : -1;
    idxr[2] = (6 < KVOL && mv) ? __ldg(nmap + (size_t)6 * N + mrow) : -1;

#pragma unroll
    for (int k = 0; k < KVOL; ++k) {
        // gather k+3 from ring slot (k+3)&3, then refill slot with k+7's idx
        uint4 pA = make_uint4(0,0,0,0), pB = pA, pC = pA, pD = pA;
        if (k + 3 < KVOL) gather4(pA, pB, pC, pD, in, idxr[(k + 3) & 3], gid, tg);
        idxr[(k + 3) & 3] = (k + 7 < KVOL && mv)
                          ? __ldg(nmap + (size_t)(k + 7) * N + mrow) : -1;

        const float4* wb = Wp + (size_t)k * 128 + lane;
#pragma unroll
        for (int ntp = 0; ntp < 2; ++ntp) {
            float4 w0 = __ldg(wb + ntp * 32);          // kc = 0
            float4 w1 = __ldg(wb + 64 + ntp * 32);     // kc = 1
            const u32 b00 = __float_as_uint(w0.x), b01 = __float_as_uint(w0.y);
            const u32 b02 = __float_as_uint(w0.z), b03 = __float_as_uint(w0.w);
            const u32 b10 = __float_as_uint(w1.x), b11 = __float_as_uint(w1.y);
            const u32 b12 = __float_as_uint(w1.z), b13 = __float_as_uint(w1.w);
            MMA_F16(acc[0][2 * ntp + 0], cA.x, cB.x, cA.y, cB.y, b00, b01);
            MMA_F16(acc[0][2 * ntp + 1], cA.x, cB.x, cA.y, cB.y, b02, b03);
            MMA_F16(acc[0][2 * ntp + 0], cA.z, cB.z, cA.w, cB.w, b10, b11);
            MMA_F16(acc[0][2 * ntp + 1], cA.z, cB.z, cA.w, cB.w, b12, b13);
            MMA_F16(acc[1][2 * ntp + 0], cC.x, cD.x, cC.y, cD.y, b00, b01);
            MMA_F16(acc[1][2 * ntp + 1], cC.x, cD.x, cC.y, cD.y, b02, b03);
            MMA_F16(acc[1][2 * ntp + 0], cC.z, cD.z, cC.w, cD.w, b10, b11);
            MMA_F16(acc[1][2 * ntp + 1], cC.z, cD.z, cC.w, cD.w, b12, b13);
        }
        cA = n1A; cB = n1B; cC = n1C; cD = n1D;
        n1A = n2A; n1B = n2B; n1C = n2C; n1D = n2D;
        n2A = pA;  n2B = pB;  n2C = pC;  n2D = pD;
    }

    // ---- epilogue: store + fused BN stats (stats from fp32 accumulators) ----
#pragma unroll
    for (int mt = 0; mt < 2; ++mt) {
        const int r0 = mbase + wid * 32 + mt * 16 + gid;
        const int r1 = r0 + 8;
        if (OUT_HALF) {
            __half* out = (__half*)out_v;
            uint4 o0, o1;
            o0.x = pack_h2(acc[mt][0][0], acc[mt][0][1]);
            o0.y = pack_h2(acc[mt][1][0], acc[mt][1][1]);
            o0.z = pack_h2(acc[mt][2][0], acc[mt][2][1]);
            o0.w = pack_h2(acc[mt][3][0], acc[mt][3][1]);
            o1.x = pack_h2(acc[mt][0][2], acc[mt][0][3]);
            o1.y = pack_h2(acc[mt][1][2], acc[mt][1][3]);
            o1.z = pack_h2(acc[mt][2][2], acc[mt][2][3]);
            o1.w = pack_h2(acc[mt][3][2], acc[mt][3][3]);
            if (r0 < N) ((uint4*)out)[(size_t)r0 * 4 + tg] = o0;
            if (r1 < N) ((uint4*)out)[(size_t)r1 * 4 + tg] = o1;
        } else {
            float* out = (float*)out_v;
#pragma unroll
            for (int nt = 0; nt < 4; ++nt) {
                int c = nt * 8 + tg * 2;
                if (r0 < N) *(float2*)(out + (size_t)r0 * 32 + c) =
                    make_float2(acc[mt][nt][0], acc[mt][nt][1]);
                if (r1 < N) *(float2*)(out + (size_t)r1 * 32 + c) =
                    make_float2(acc[mt][nt][2], acc[mt][nt][3]);
            }
        }
    }

    float s[4][2], q[4][2];
#pragma unroll
    for (int nt = 0; nt < 4; ++nt)
#pragma unroll
        for (int j = 0; j < 2; ++j) {
            float v0 = acc[0][nt][j], v1 = acc[0][nt][2 + j];
            float v2 = acc[1][nt][j], v3 = acc[1][nt][2 + j];
            s[nt][j] = (v0 + v1) + (v2 + v3);
            q[nt][j] = (v0 * v0 + v1 * v1) + (v2 * v2 + v3 * v3);
        }
#pragma unroll
    for (int off = 4; off < 32; off <<= 1)
#pragma unroll
        for (int nt = 0; nt < 4; ++nt)
#pragma unroll
            for (int j = 0; j < 2; ++j) {
                s[nt][j] += __shfl_xor_sync(0xffffffffu, s[nt][j], off);
                q[nt][j] += __shfl_xor_sync(0xffffffffu, q[nt][j], off);
            }
    if (lane < 4) {
#pragma unroll
        for (int nt = 0; nt < 4; ++nt)
#pragma unroll
            for (int j = 0; j < 2; ++j) {
                int c = nt * 8 + tg * 2 + j;
                Red[wid * 64 + c]      = s[nt][j];
                Red[wid * 64 + 32 + c] = q[nt][j];
            }
    }
    __syncthreads();
    if (tid < 64) {
        int plane = tid >> 5, c = tid & 31;
        float v = 0.f;
#pragma unroll
        for (int i = 0; i < 8; ++i) v += Red[i * 64 + plane * 32 + c];
        atomicAdd(stats + plane * 32 + c, v);
    }
}

// ---------------------------------------------------------------------------
__global__ __launch_bounds__(256)
void bnelu_h2h_kernel(const __half* __restrict__ x, __half* __restrict__ y,
                      const float* __restrict__ stats,
                      const float* __restrict__ gamma, const float* __restrict__ beta,
                      int N)
{
    __shared__ float sc[32], sh[32];
    if (threadIdx.x < 32) {
        int c = threadIdx.x;
        float inv  = 1.0f / (float)N;
        float mean = stats[c] * inv;
        float var  = stats[32 + c] * inv - mean * mean;
        float sfac = rsqrtf(var + EPS) * gamma[c];
        sc[c] = sfac;
        sh[c] = beta[c] - mean * sfac;
    }
    __syncthreads();

    int i = blockIdx.x * blockDim.x + threadIdx.x;
    int row = i >> 2, tg = i & 3;
    if (row >= N) return;
    uint4 v = __ldg((const uint4*)x + (size_t)row * 4 + tg);
    uint4 o;
#pragma unroll
    for (int qd = 0; qd < 4; ++qd) {
        int c = tg * 2 + qd * 8;
        __half2 h = *(__half2*)(((u32*)&v) + qd);
        float2 f = __half22float2(h);
        float z0 = f.x * sc[c] + sh[c];
        float z1 = f.y * sc[c + 1] + sh[c + 1];
        z0 = (z0 > 0.f) ? z0 : expm1f(z0);
        z1 = (z1 > 0.f) ? z1 : expm1f(z1);
        ((u32*)&o)[qd] = pack_h2(z0, z1);
    }
    ((uint4*)y)[(size_t)row * 4 + tg] = o;
}

// ---------------------------------------------------------------------------
__global__ __launch_bounds__(256)
void bnelu_f32_kernel(const float* __restrict__ x, float* __restrict__ y,
                      const float* __restrict__ stats,
                      const float* __restrict__ gamma, const float* __restrict__ beta,
                      int N)
{
    __shared__ float sc[32], sh[32];
    if (threadIdx.x < 32) {
        int c = threadIdx.x;
        float inv  = 1.0f / (float)N;
        float mean = stats[c] * inv;
        float var  = stats[32 + c] * inv - mean * mean;
        float sfac = rsqrtf(var + EPS) * gamma[c];
        sc[c] = sfac;
        sh[c] = beta[c] - mean * sfac;
    }
    __syncthreads();
    const int total4 = N * 8;
    for (int i = blockIdx.x * blockDim.x + threadIdx.x; i < total4;
         i += gridDim.x * blockDim.x) {
        float4 v = ((const float4*)x)[i];
        int c = (i * 4) & 31;
        float z;
        z = v.x * sc[c + 0] + sh[c + 0]; v.x = (z > 0.f) ? z : expm1f(z);
        z = v.y * sc[c + 1] + sh[c + 1]; v.y = (z > 0.f) ? z : expm1f(z);
        z = v.z * sc[c + 2] + sh[c + 2]; v.z = (z > 0.f) ? z : expm1f(z);
        z = v.w * sc[c + 3] + sh[c + 3]; v.w = (z > 0.f) ? z : expm1f(z);
        ((float4*)y)[i] = v;
    }
}

// ---------------------------------------------------------------------------
extern "C" void kernel_launch(void* const* d_in, const int* in_sizes, int n_in,
                              void* d_out, int out_size)
{
    const float* feats = (const float*)d_in[0];
    const float* W1    = (const float*)d_in[1];
    const float* g1    = (const float*)d_in[2];
    const float* b1    = (const float*)d_in[3];
    const float* W2    = (const float*)d_in[4];
    const float* g2    = (const float*)d_in[5];
    const float* b2    = (const float*)d_in[6];
    const float* W3    = (const float*)d_in[7];
    const float* g3    = (const float*)d_in[8];
    const float* b3    = (const float*)d_in[9];
    const int*   nmap3 = (const int*)d_in[10];
    const int*   nmap2 = (const int*)d_in[11];

    const int N = in_sizes[0] / 32;
    const int ntiles = (N + 255) / 256;
    const int nquads = (N * 4 + 255) / 256;

    __half *hA, *hB;
    float *F, *stats;
    float4* Wp;
    cudaGetSymbolAddress((void**)&hA,    g_hA);
    cudaGetSymbolAddress((void**)&hB,    g_hB);
    cudaGetSymbolAddress((void**)&F,     g_F);
    cudaGetSymbolAddress((void**)&stats, g_stats);
    cudaGetSymbolAddress((void**)&Wp,    g_Wp);

    cudaMemsetAsync(stats, 0, 3 * 64 * sizeof(float), 0);
    prep_weights<<<27, 128>>>(W1, Wp + 0 * 128);
    prep_weights<<< 8, 128>>>(W2, Wp + 27 * 128);
    prep_weights<<<27, 128>>>(W3, Wp + 35 * 128);
    cvt_half_kernel<<<nquads, 256>>>(feats, hA, N);

    conv_mma<27, true><<<ntiles, 256>>>(hA, nmap3, Wp + 0 * 128, hB, stats + 0, N);
    bnelu_h2h_kernel<<<nquads, 256>>>(hB, hB, stats + 0, g1, b1, N);

    conv_mma<8, true><<<ntiles, 256>>>(hB, nmap2, Wp + 27 * 128, hA, stats + 64, N);
    bnelu_h2h_kernel<<<nquads, 256>>>(hA, hA, stats + 64, g2, b2, N);

    conv_mma<27, false><<<ntiles, 256>>>(hA, nmap3, Wp + 35 * 128, F, stats + 128, N);
    bnelu_f32_kernel<<<2048, 256>>>(F, (float*)d_out, stats + 128, g3, b3, N);
}

// round 15
// speedup vs baseline: 1.1328x; 1.0018x over previous
#include <cuda_runtime.h>
#include <cuda_fp16.h>
#include <math.h>
#include <stdint.h>

// ---------------------------------------------------------------------------
// CompletionNet via warp-level fp16 mma.sync (m16n8k16, fp32 accum).
// R13 = R10 (best) with the gather pipeline deepened to distance 3.
// M=32 warp tile, register-direct fragment gather, idx ring depth 4
// (idx loaded 4 iterations before its shuffle).
// Layers 1-2 produce permuted fp16; layer 3 produces fp32.
// ---------------------------------------------------------------------------

#define NMAX 500000
#define EPS  1e-5f

__device__ __half g_hA[NMAX * 32];
__device__ __half g_hB[NMAX * 32];
__device__ float  g_F[NMAX * 32];
__device__ float  g_stats[3 * 64];
__device__ float4 g_Wp[62 * 128];

typedef unsigned int u32;

__device__ __forceinline__ u32 pack_h2(float lo, float hi) {
    u32 r; asm("cvt.rn.f16x2.f32 %0, %1, %2;" : "=r"(r) : "f"(hi), "f"(lo)); return r;
}

#define MMA_F16(d, a0, a1, a2, a3, b0, b1)                                      \
    asm volatile("mma.sync.aligned.m16n8k16.row.col.f32.f16.f16.f32 "           \
                 "{%0,%1,%2,%3}, {%4,%5,%6,%7}, {%8,%9}, {%0,%1,%2,%3};"        \
                 : "+f"(d[0]), "+f"(d[1]), "+f"(d[2]), "+f"(d[3])               \
                 : "r"(a0), "r"(a1), "r"(a2), "r"(a3), "r"(b0), "r"(b1))

// ---------------------------------------------------------------------------
__global__ void prep_weights(const float* __restrict__ W, float4* __restrict__ dst) {
    int k = blockIdx.x;
    int t = threadIdx.x;                 // 0..127
    int lane = t & 31, ntp = (t >> 5) & 1, kc = t >> 6;
    int r  = lane >> 2;
    int cL = (lane & 3) * 2;
    int co0 = (2 * ntp) * 8 + r;
    int co1 = co0 + 8;
    const float* Wk = W + k * 1024 + kc * 16 * 32;
    u32 p0 = pack_h2(Wk[(cL + 0) * 32 + co0], Wk[(cL + 1) * 32 + co0]);
    u32 p1 = pack_h2(Wk[(cL + 8) * 32 + co0], Wk[(cL + 9) * 32 + co0]);
    u32 p2 = pack_h2(Wk[(cL + 0) * 32 + co1], Wk[(cL + 1) * 32 + co1]);
    u32 p3 = pack_h2(Wk[(cL + 8) * 32 + co1], Wk[(cL + 9) * 32 + co1]);
    float4 v;
    v.x = __uint_as_float(p0); v.y = __uint_as_float(p1);
    v.z = __uint_as_float(p2); v.w = __uint_as_float(p3);
    dst[k * 128 + kc * 64 + ntp * 32 + lane] = v;
}

// ---------------------------------------------------------------------------
__global__ __launch_bounds__(256)
void cvt_half_kernel(const float* __restrict__ x, __half* __restrict__ y, int N)
{
    int i = blockIdx.x * blockDim.x + threadIdx.x;
    int row = i >> 2, tg = i & 3;
    if (row >= N) return;
    const float2* src = (const float2*)(x + (size_t)row * 32);
    float2 v0 = __ldg(src + tg);
    float2 v1 = __ldg(src + tg + 4);
    float2 v2 = __ldg(src + tg + 8);
    float2 v3 = __ldg(src + tg + 12);
    uint4 o;
    o.x = pack_h2(v0.x, v0.y);
    o.y = pack_h2(v1.x, v1.y);
    o.z = pack_h2(v2.x, v2.y);
    o.w = pack_h2(v3.x, v3.y);
    ((uint4*)y)[(size_t)row * 4 + tg] = o;
}

// ---------------------------------------------------------------------------
__device__ __forceinline__ void gather4(uint4& a, uint4& b, uint4& c, uint4& d,
                                        const __half* __restrict__ in,
                                        int idx, int gid, int tg)
{
    const int iA = __shfl_sync(0xffffffffu, idx, gid);
    const int iB = __shfl_sync(0xffffffffu, idx, 8 + gid);
    const int iC = __shfl_sync(0xffffffffu, idx, 16 + gid);
    const int iD = __shfl_sync(0xffffffffu, idx, 24 + gid);
    a = make_uint4(0u, 0u, 0u, 0u); b = a; c = a; d = a;
    if (iA >= 0) a = __ldg((const uint4*)(in + (size_t)iA * 32) + tg);
    if (iB >= 0) b = __ldg((const uint4*)(in + (size_t)iB * 32) + tg);
    if (iC >= 0) c = __ldg((const uint4*)(in + (size_t)iC * 32) + tg);
    if (iD >= 0) d = __ldg((const uint4*)(in + (size_t)iD * 32) + tg);
}

// ---------------------------------------------------------------------------
// conv: block = 256 threads (8 warps), tile = 256 voxels x 32 out-channels.
// Warp tile M=32. Gather distance-3 (4 live fragment sets), idx ring depth 4.
// Ring invariant entering iteration k: slots hold idx for offsets {k+3..k+6}.
// OUT_HALF: write permuted fp16 (one uint4 per row-quarter); else fp32.
// ---------------------------------------------------------------------------
template<int KVOL, bool OUT_HALF>
__global__ __launch_bounds__(256, 2)
void conv_mma(const __half* __restrict__ in, const int* __restrict__ nmap,
              const float4* __restrict__ Wp, void* __restrict__ out_v,
              float* __restrict__ stats, int N)
{
    __shared__ float Red[8 * 64];

    const int tid  = threadIdx.x;
    const int wid  = tid >> 5, lane = tid & 31;
    const int gid  = lane >> 2, tg = lane & 3;
    const int mbase = blockIdx.x * 256;
    const int mrow  = mbase + wid * 32 + lane;
    const bool mv   = (mrow < N);

    float acc[2][4][4];
#pragma unroll
    for (int mt = 0; mt < 2; ++mt)
#pragma unroll
        for (int nt = 0; nt < 4; ++nt)
#pragma unroll
            for (int j = 0; j < 4; ++j) acc[mt][nt][j] = 0.f;

    // ---- idx ring depth 4: prime with offsets 0..3 ----
    int idxr[4];
#pragma unroll
    for (int j = 0; j < 4; ++j)
        idxr[j] = (j < KVOL && mv) ? __ldg(nmap + (size_t)j * N + mrow) : -1;

    // ---- prime 3 gather stages (consumes ring offsets 0,1,2) ----
    uint4 cA, cB, cC, cD;
    gather4(cA, cB, cC, cD, in, idxr[0], gid, tg);
    uint4 n1A = make_uint4(0,0,0,0), n1B = n1A, n1C = n1A, n1D = n1A;
    if (KVOL > 1) gather4(n1A, n1B, n1C, n1D, in, idxr[1], gid, tg);
    uint4 n2A = make_uint4(0,0,0,0), n2B = n2A, n2C = n2A, n2D = n2A;
    if (KVOL > 2) gather4(n2A, n2B, n2C, n2D, in, idxr[2], gid, tg);

    // ---- refill consumed slots with offsets 4,5,6 ----
    idxr[0] = (4 < KVOL && mv) ? __ldg(nmap + (size_t)4 * N + mrow) : -1;
    idxr[1] = (5 < KVOL && mv) ? __ldg(nmap + (size_t)5 * N + mrow) : -1;
    idxr[2] = (6 < KVOL && mv) ? __ldg(nmap + (size_t)6 * N + mrow) : -1;

#pragma unroll
    for (int k = 0; k < KVOL; ++k) {
        // gather k+3 from ring slot (k+3)&3, then refill slot with k+7's idx
        uint4 pA = make_uint4(0,0,0,0), pB = pA, pC = pA, pD = pA;
        if (k + 3 < KVOL) gather4(pA, pB, pC, pD, in, idxr[(k + 3) & 3], gid, tg);
        idxr[(k + 3) & 3] = (k + 7 < KVOL && mv)
                          ? __ldg(nmap + (size_t)(k + 7) * N + mrow) : -1;

        const float4* wb = Wp + (size_t)k * 128 + lane;
#pragma unroll
        for (int ntp = 0; ntp < 2; ++ntp) {
            float4 w0 = __ldg(wb + ntp * 32);          // kc = 0
            float4 w1 = __ldg(wb + 64 + ntp * 32);     // kc = 1
            const u32 b00 = __float_as_uint(w0.x), b01 = __float_as_uint(w0.y);
            const u32 b02 = __float_as_uint(w0.z), b03 = __float_as_uint(w0.w);
            const u32 b10 = __float_as_uint(w1.x), b11 = __float_as_uint(w1.y);
            const u32 b12 = __float_as_uint(w1.z), b13 = __float_as_uint(w1.w);
            MMA_F16(acc[0][2 * ntp + 0], cA.x, cB.x, cA.y, cB.y, b00, b01);
            MMA_F16(acc[0][2 * ntp + 1], cA.x, cB.x, cA.y, cB.y, b02, b03);
            MMA_F16(acc[0][2 * ntp + 0], cA.z, cB.z, cA.w, cB.w, b10, b11);
            MMA_F16(acc[0][2 * ntp + 1], cA.z, cB.z, cA.w, cB.w, b12, b13);
            MMA_F16(acc[1][2 * ntp + 0], cC.x, cD.x, cC.y, cD.y, b00, b01);
            MMA_F16(acc[1][2 * ntp + 1], cC.x, cD.x, cC.y, cD.y, b02, b03);
            MMA_F16(acc[1][2 * ntp + 0], cC.z, cD.z, cC.w, cD.w, b10, b11);
            MMA_F16(acc[1][2 * ntp + 1], cC.z, cD.z, cC.w, cD.w, b12, b13);
        }
        cA = n1A; cB = n1B; cC = n1C; cD = n1D;
        n1A = n2A; n1B = n2B; n1C = n2C; n1D = n2D;
        n2A = pA;  n2B = pB;  n2C = pC;  n2D = pD;
    }

    // ---- epilogue: store + fused BN stats (stats from fp32 accumulators) ----
#pragma unroll
    for (int mt = 0; mt < 2; ++mt) {
        const int r0 = mbase + wid * 32 + mt * 16 + gid;
        const int r1 = r0 + 8;
        if (OUT_HALF) {
            __half* out = (__half*)out_v;
            uint4 o0, o1;
            o0.x = pack_h2(acc[mt][0][0], acc[mt][0][1]);
            o0.y = pack_h2(acc[mt][1][0], acc[mt][1][1]);
            o0.z = pack_h2(acc[mt][2][0], acc[mt][2][1]);
            o0.w = pack_h2(acc[mt][3][0], acc[mt][3][1]);
            o1.x = pack_h2(acc[mt][0][2], acc[mt][0][3]);
            o1.y = pack_h2(acc[mt][1][2], acc[mt][1][3]);
            o1.z = pack_h2(acc[mt][2][2], acc[mt][2][3]);
            o1.w = pack_h2(acc[mt][3][2], acc[mt][3][3]);
            if (r0 < N) ((uint4*)out)[(size_t)r0 * 4 + tg] = o0;
            if (r1 < N) ((uint4*)out)[(size_t)r1 * 4 + tg] = o1;
        } else {
            float* out = (float*)out_v;
#pragma unroll
            for (int nt = 0; nt < 4; ++nt) {
                int c = nt * 8 + tg * 2;
                if (r0 < N) *(float2*)(out + (size_t)r0 * 32 + c) =
                    make_float2(acc[mt][nt][0], acc[mt][nt][1]);
                if (r1 < N) *(float2*)(out + (size_t)r1 * 32 + c) =
                    make_float2(acc[mt][nt][2], acc[mt][nt][3]);
            }
        }
    }

    float s[4][2], q[4][2];
#pragma unroll
    for (int nt = 0; nt < 4; ++nt)
#pragma unroll
        for (int j = 0; j < 2; ++j) {
            float v0 = acc[0][nt][j], v1 = acc[0][nt][2 + j];
            float v2 = acc[1][nt][j], v3 = acc[1][nt][2 + j];
            s[nt][j] = (v0 + v1) + (v2 + v3);
            q[nt][j] = (v0 * v0 + v1 * v1) + (v2 * v2 + v3 * v3);
        }
#pragma unroll
    for (int off = 4; off < 32; off <<= 1)
#pragma unroll
        for (int nt = 0; nt < 4; ++nt)
#pragma unroll
            for (int j = 0; j < 2; ++j) {
                s[nt][j] += __shfl_xor_sync(0xffffffffu, s[nt][j], off);
                q[nt][j] += __shfl_xor_sync(0xffffffffu, q[nt][j], off);
            }
    if (lane < 4) {
#pragma unroll
        for (int nt = 0; nt < 4; ++nt)
#pragma unroll
            for (int j = 0; j < 2; ++j) {
                int c = nt * 8 + tg * 2 + j;
                Red[wid * 64 + c]      = s[nt][j];
                Red[wid * 64 + 32 + c] = q[nt][j];
            }
    }
    __syncthreads();
    if (tid < 64) {
        int plane = tid >> 5, c = tid & 31;
        float v = 0.f;
#pragma unroll
        for (int i = 0; i < 8; ++i) v += Red[i * 64 + plane * 32 + c];
        atomicAdd(stats + plane * 32 + c, v);
    }
}

// ---------------------------------------------------------------------------
__global__ __launch_bounds__(256)
void bnelu_h2h_kernel(const __half* __restrict__ x, __half* __restrict__ y,
                      const float* __restrict__ stats,
                      const float* __restrict__ gamma, const float* __restrict__ beta,
                      int N)
{
    __shared__ float sc[32], sh[32];
    if (threadIdx.x < 32) {
        int c = threadIdx.x;
        float inv  = 1.0f / (float)N;
        float mean = stats[c] * inv;
        float var  = stats[32 + c] * inv - mean * mean;
        float sfac = rsqrtf(var + EPS) * gamma[c];
        sc[c] = sfac;
        sh[c] = beta[c] - mean * sfac;
    }
    __syncthreads();

    int i = blockIdx.x * blockDim.x + threadIdx.x;
    int row = i >> 2, tg = i & 3;
    if (row >= N) return;
    uint4 v = __ldg((const uint4*)x + (size_t)row * 4 + tg);
    uint4 o;
#pragma unroll
    for (int qd = 0; qd < 4; ++qd) {
        int c = tg * 2 + qd * 8;
        __half2 h = *(__half2*)(((u32*)&v) + qd);
        float2 f = __half22float2(h);
        float z0 = f.x * sc[c] + sh[c];
        float z1 = f.y * sc[c + 1] + sh[c + 1];
        z0 = (z0 > 0.f) ? z0 : expm1f(z0);
        z1 = (z1 > 0.f) ? z1 : expm1f(z1);
        ((u32*)&o)[qd] = pack_h2(z0, z1);
    }
    ((uint4*)y)[(size_t)row * 4 + tg] = o;
}

// ---------------------------------------------------------------------------
__global__ __launch_bounds__(256)
void bnelu_f32_kernel(const float* __restrict__ x, float* __restrict__ y,
                      const float* __restrict__ stats,
                      const float* __restrict__ gamma, const float* __restrict__ beta,
                      int N)
{
    __shared__ float sc[32], sh[32];
    if (threadIdx.x < 32) {
        int c = threadIdx.x;
        float inv  = 1.0f / (float)N;
        float mean = stats[c] * inv;
        float var  = stats[32 + c] * inv - mean * mean;
        float sfac = rsqrtf(var + EPS) * gamma[c];
        sc[c] = sfac;
        sh[c] = beta[c] - mean * sfac;
    }
    __syncthreads();
    const int total4 = N * 8;
    for (int i = blockIdx.x * blockDim.x + threadIdx.x; i < total4;
         i += gridDim.x * blockDim.x) {
        float4 v = ((const float4*)x)[i];
        int c = (i * 4) & 31;
        float z;
        z = v.x * sc[c + 0] + sh[c + 0]; v.x = (z > 0.f) ? z : expm1f(z);
        z = v.y * sc[c + 1] + sh[c + 1]; v.y = (z > 0.f) ? z : expm1f(z);
        z = v.z * sc[c + 2] + sh[c + 2]; v.z = (z > 0.f) ? z : expm1f(z);
        z = v.w * sc[c + 3] + sh[c + 3]; v.w = (z > 0.f) ? z : expm1f(z);
        ((float4*)y)[i] = v;
    }
}

// ---------------------------------------------------------------------------
extern "C" void kernel_launch(void* const* d_in, const int* in_sizes, int n_in,
                              void* d_out, int out_size)
{
    const float* feats = (const float*)d_in[0];
    const float* W1    = (const float*)d_in[1];
    const float* g1    = (const float*)d_in[2];
    const float* b1    = (const float*)d_in[3];
    const float* W2    = (const float*)d_in[4];
    const float* g2    = (const float*)d_in[5];
    const float* b2    = (const float*)d_in[6];
    const float* W3    = (const float*)d_in[7];
    const float* g3    = (const float*)d_in[8];
    const float* b3    = (const float*)d_in[9];
    const int*   nmap3 = (const int*)d_in[10];
    const int*   nmap2 = (const int*)d_in[11];

    const int N = in_sizes[0] / 32;
    const int ntiles = (N + 255) / 256;
    const int nquads = (N * 4 + 255) / 256;

    __half *hA, *hB;
    float *F, *stats;
    float4* Wp;
    cudaGetSymbolAddress((void**)&hA,    g_hA);
    cudaGetSymbolAddress((void**)&hB,    g_hB);
    cudaGetSymbolAddress((void**)&F,     g_F);
    cudaGetSymbolAddress((void**)&stats, g_stats);
    cudaGetSymbolAddress((void**)&Wp,    g_Wp);

    cudaMemsetAsync(stats, 0, 3 * 64 * sizeof(float), 0);
    prep_weights<<<27, 128>>>(W1, Wp + 0 * 128);
    prep_weights<<< 8, 128>>>(W2, Wp + 27 * 128);
    prep_weights<<<27, 128>>>(W3, Wp + 35 * 128);
    cvt_half_kernel<<<nquads, 256>>>(feats, hA, N);

    conv_mma<27, true><<<ntiles, 256>>>(hA, nmap3, Wp + 0 * 128, hB, stats + 0, N);
    bnelu_h2h_kernel<<<nquads, 256>>>(hB, hB, stats + 0, g1, b1, N);

    conv_mma<8, true><<<ntiles, 256>>>(hB, nmap2, Wp + 27 * 128, hA, stats + 64, N);
    bnelu_h2h_kernel<<<nquads, 256>>>(hA, hA, stats + 64, g2, b2, N);

    conv_mma<27, false><<<ntiles, 256>>>(hA, nmap3, Wp + 35 * 128, F, stats + 128, N);
    bnelu_f32_kernel<<<2048, 256>>>(F, (float*)d_out, stats + 128, g3, b3, N);
}

// round 16
// speedup vs baseline: 1.1890x; 1.0495x over previous
#include <cuda_runtime.h>
#include <cuda_fp16.h>
#include <math.h>
#include <stdint.h>

// ---------------------------------------------------------------------------
// CompletionNet via warp-level fp16 mma.sync (m16n8k16, fp32 accum).
// R16 = R10 (best: M=32 warp tile, register gather distance-2, idx ring 5)
// + all three convs output permuted fp16 (layer-3 included)
// + final BN+ELU reads fp16 / writes fp32 with unpermute folded in
// + single fused weight-prep launch; stats zeroing folded into cvt pass.
// ---------------------------------------------------------------------------

#define NMAX 500000
#define EPS  1e-5f

__device__ __half g_hA[NMAX * 32];
__device__ __half g_hB[NMAX * 32];
__device__ float  g_stats[3 * 64];
__device__ float4 g_Wp[62 * 128];

typedef unsigned int u32;

__device__ __forceinline__ u32 pack_h2(float lo, float hi) {
    u32 r; asm("cvt.rn.f16x2.f32 %0, %1, %2;" : "=r"(r) : "f"(hi), "f"(lo)); return r;
}

#define MMA_F16(d, a0, a1, a2, a3, b0, b1)                                      \
    asm volatile("mma.sync.aligned.m16n8k16.row.col.f32.f16.f16.f32 "           \
                 "{%0,%1,%2,%3}, {%4,%5,%6,%7}, {%8,%9}, {%0,%1,%2,%3};"        \
                 : "+f"(d[0]), "+f"(d[1]), "+f"(d[2]), "+f"(d[3])               \
                 : "r"(a0), "r"(a1), "r"(a2), "r"(a3), "r"(b0), "r"(b1))

// ---------------------------------------------------------------------------
// Fused weight prep: 62 blocks; 0..26 -> W1, 27..34 -> W2, 35..61 -> W3.
// Thread t = kc*64 + ntp*32 + lane writes one float4 (4x half2 fragments).
// ---------------------------------------------------------------------------
__global__ void prep_weights_all(const float* __restrict__ W1,
                                 const float* __restrict__ W2,
                                 const float* __restrict__ W3,
                                 float4* __restrict__ dst)
{
    int kb = blockIdx.x;
    const float* W;
    int k;
    if (kb < 27)      { W = W1; k = kb; }
    else if (kb < 35) { W = W2; k = kb - 27; }
    else              { W = W3; k = kb - 35; }

    int t = threadIdx.x;                 // 0..127
    int lane = t & 31, ntp = (t >> 5) & 1, kc = t >> 6;
    int r  = lane >> 2;
    int cL = (lane & 3) * 2;
    int co0 = (2 * ntp) * 8 + r;
    int co1 = co0 + 8;
    const float* Wk = W + k * 1024 + kc * 16 * 32;
    u32 p0 = pack_h2(Wk[(cL + 0) * 32 + co0], Wk[(cL + 1) * 32 + co0]);
    u32 p1 = pack_h2(Wk[(cL + 8) * 32 + co0], Wk[(cL + 9) * 32 + co0]);
    u32 p2 = pack_h2(Wk[(cL + 0) * 32 + co1], Wk[(cL + 1) * 32 + co1]);
    u32 p3 = pack_h2(Wk[(cL + 8) * 32 + co1], Wk[(cL + 9) * 32 + co1]);
    float4 v;
    v.x = __uint_as_float(p0); v.y = __uint_as_float(p1);
    v.z = __uint_as_float(p2); v.w = __uint_as_float(p3);
    dst[kb * 128 + kc * 64 + ntp * 32 + lane] = v;
}

// ---------------------------------------------------------------------------
// feats fp32 -> permuted fp16; block 0 also zeroes the stats buffer.
// ---------------------------------------------------------------------------
__global__ __launch_bounds__(256)
void cvt_half_kernel(const float* __restrict__ x, __half* __restrict__ y,
                     float* __restrict__ stats, int N)
{
    if (blockIdx.x == 0 && threadIdx.x < 192) stats[threadIdx.x] = 0.f;
    int i = blockIdx.x * blockDim.x + threadIdx.x;
    int row = i >> 2, tg = i & 3;
    if (row >= N) return;
    const float2* src = (const float2*)(x + (size_t)row * 32);
    float2 v0 = __ldg(src + tg);
    float2 v1 = __ldg(src + tg + 4);
    float2 v2 = __ldg(src + tg + 8);
    float2 v3 = __ldg(src + tg + 12);
    uint4 o;
    o.x = pack_h2(v0.x, v0.y);
    o.y = pack_h2(v1.x, v1.y);
    o.z = pack_h2(v2.x, v2.y);
    o.w = pack_h2(v3.x, v3.y);
    ((uint4*)y)[(size_t)row * 4 + tg] = o;
}

// ---------------------------------------------------------------------------
__device__ __forceinline__ void gather4(uint4& a, uint4& b, uint4& c, uint4& d,
                                        const __half* __restrict__ in,
                                        int idx, int gid, int tg)
{
    const int iA = __shfl_sync(0xffffffffu, idx, gid);
    const int iB = __shfl_sync(0xffffffffu, idx, 8 + gid);
    const int iC = __shfl_sync(0xffffffffu, idx, 16 + gid);
    const int iD = __shfl_sync(0xffffffffu, idx, 24 + gid);
    a = make_uint4(0u, 0u, 0u, 0u); b = a; c = a; d = a;
    if (iA >= 0) a = __ldg((const uint4*)(in + (size_t)iA * 32) + tg);
    if (iB >= 0) b = __ldg((const uint4*)(in + (size_t)iB * 32) + tg);
    if (iC >= 0) c = __ldg((const uint4*)(in + (size_t)iC * 32) + tg);
    if (iD >= 0) d = __ldg((const uint4*)(in + (size_t)iD * 32) + tg);
}

// ---------------------------------------------------------------------------
// conv: block = 256 threads (8 warps), tile = 256 voxels x 32 out-channels.
// Warp tile M=32, gather distance-2, idx ring depth 5 (R10 structure).
// Output: permuted fp16 (one uint4 per row-quarter). BN stats fused (fp32).
// ---------------------------------------------------------------------------
template<int KVOL>
__global__ __launch_bounds__(256, 2)
void conv_mma(const __half* __restrict__ in, const int* __restrict__ nmap,
              const float4* __restrict__ Wp, __half* __restrict__ out,
              float* __restrict__ stats, int N)
{
    __shared__ float Red[8 * 64];

    const int tid  = threadIdx.x;
    const int wid  = tid >> 5, lane = tid & 31;
    const int gid  = lane >> 2, tg = lane & 3;
    const int mbase = blockIdx.x * 256;
    const int mrow  = mbase + wid * 32 + lane;
    const bool mv   = (mrow < N);

    float acc[2][4][4];
#pragma unroll
    for (int mt = 0; mt < 2; ++mt)
#pragma unroll
        for (int nt = 0; nt < 4; ++nt)
#pragma unroll
            for (int j = 0; j < 4; ++j) acc[mt][nt][j] = 0.f;

    // ---- idx ring: depth 5 ----
    int idxr[5];
#pragma unroll
    for (int j = 0; j < 5; ++j)
        idxr[j] = (j < KVOL && mv) ? __ldg(nmap + (size_t)j * N + mrow) : -1;

    // ---- prime 2 gather stages ----
    uint4 cA, cB, cC, cD;
    gather4(cA, cB, cC, cD, in, idxr[0], gid, tg);
    uint4 nA = make_uint4(0,0,0,0), nB = nA, nC = nA, nD = nA;
    if (KVOL > 1) gather4(nA, nB, nC, nD, in, idxr[1], gid, tg);

#pragma unroll
    for (int k = 0; k < KVOL; ++k) {
        // gather k+2 (idx loaded 3+ iterations ago -> shfl does not stall)
        uint4 pA = make_uint4(0,0,0,0), pB = pA, pC = pA, pD = pA;
        if (k + 2 < KVOL) gather4(pA, pB, pC, pD, in, idxr[(k + 2) % 5], gid, tg);
        // refill ring slot (idx for offset k no longer needed)
        idxr[k % 5] = (k + 5 < KVOL && mv)
                    ? __ldg(nmap + (size_t)(k + 5) * N + mrow) : -1;

        const float4* wb = Wp + (size_t)k * 128 + lane;
#pragma unroll
        for (int ntp = 0; ntp < 2; ++ntp) {
            float4 w0 = __ldg(wb + ntp * 32);          // kc = 0
            float4 w1 = __ldg(wb + 64 + ntp * 32);     // kc = 1
            const u32 b00 = __float_as_uint(w0.x), b01 = __float_as_uint(w0.y);
            const u32 b02 = __float_as_uint(w0.z), b03 = __float_as_uint(w0.w);
            const u32 b10 = __float_as_uint(w1.x), b11 = __float_as_uint(w1.y);
            const u32 b12 = __float_as_uint(w1.z), b13 = __float_as_uint(w1.w);
            MMA_F16(acc[0][2 * ntp + 0], cA.x, cB.x, cA.y, cB.y, b00, b01);
            MMA_F16(acc[0][2 * ntp + 1], cA.x, cB.x, cA.y, cB.y, b02, b03);
            MMA_F16(acc[0][2 * ntp + 0], cA.z, cB.z, cA.w, cB.w, b10, b11);
            MMA_F16(acc[0][2 * ntp + 1], cA.z, cB.z, cA.w, cB.w, b12, b13);
            MMA_F16(acc[1][2 * ntp + 0], cC.x, cD.x, cC.y, cD.y, b00, b01);
            MMA_F16(acc[1][2 * ntp + 1], cC.x, cD.x, cC.y, cD.y, b02, b03);
            MMA_F16(acc[1][2 * ntp + 0], cC.z, cD.z, cC.w, cD.w, b10, b11);
            MMA_F16(acc[1][2 * ntp + 1], cC.z, cD.z, cC.w, cD.w, b12, b13);
        }
        cA = nA; cB = nB; cC = nC; cD = nD;
        nA = pA; nB = pB; nC = pC; nD = pD;
    }

    // ---- epilogue: permuted fp16 store + fused BN stats (fp32 accum) ----
#pragma unroll
    for (int mt = 0; mt < 2; ++mt) {
        const int r0 = mbase + wid * 32 + mt * 16 + gid;
        const int r1 = r0 + 8;
        uint4 o0, o1;
        o0.x = pack_h2(acc[mt][0][0], acc[mt][0][1]);
        o0.y = pack_h2(acc[mt][1][0], acc[mt][1][1]);
        o0.z = pack_h2(acc[mt][2][0], acc[mt][2][1]);
        o0.w = pack_h2(acc[mt][3][0], acc[mt][3][1]);
        o1.x = pack_h2(acc[mt][0][2], acc[mt][0][3]);
        o1.y = pack_h2(acc[mt][1][2], acc[mt][1][3]);
        o1.z = pack_h2(acc[mt][2][2], acc[mt][2][3]);
        o1.w = pack_h2(acc[mt][3][2], acc[mt][3][3]);
        if (r0 < N) ((uint4*)out)[(size_t)r0 * 4 + tg] = o0;
        if (r1 < N) ((uint4*)out)[(size_t)r1 * 4 + tg] = o1;
    }

    float s[4][2], q[4][2];
#pragma unroll
    for (int nt = 0; nt < 4; ++nt)
#pragma unroll
        for (int j = 0; j < 2; ++j) {
            float v0 = acc[0][nt][j], v1 = acc[0][nt][2 + j];
            float v2 = acc[1][nt][j], v3 = acc[1][nt][2 + j];
            s[nt][j] = (v0 + v1) + (v2 + v3);
            q[nt][j] = (v0 * v0 + v1 * v1) + (v2 * v2 + v3 * v3);
        }
#pragma unroll
    for (int off = 4; off < 32; off <<= 1)
#pragma unroll
        for (int nt = 0; nt < 4; ++nt)
#pragma unroll
            for (int j = 0; j < 2; ++j) {
                s[nt][j] += __shfl_xor_sync(0xffffffffu, s[nt][j], off);
                q[nt][j] += __shfl_xor_sync(0xffffffffu, q[nt][j], off);
            }
    if (lane < 4) {
#pragma unroll
        for (int nt = 0; nt < 4; ++nt)
#pragma unroll
            for (int j = 0; j < 2; ++j) {
                int c = nt * 8 + tg * 2 + j;
                Red[wid * 64 + c]      = s[nt][j];
                Red[wid * 64 + 32 + c] = q[nt][j];
            }
    }
    __syncthreads();
    if (tid < 64) {
        int plane = tid >> 5, c = tid & 31;
        float v = 0.f;
#pragma unroll
        for (int i = 0; i < 8; ++i) v += Red[i * 64 + plane * 32 + c];
        atomicAdd(stats + plane * 32 + c, v);
    }
}

// ---------------------------------------------------------------------------
// BN + ELU on permuted fp16 in -> permuted fp16 out. Thread per (row, tg).
// ---------------------------------------------------------------------------
__global__ __launch_bounds__(256)
void bnelu_h2h_kernel(const __half* __restrict__ x, __half* __restrict__ y,
                      const float* __restrict__ stats,
                      const float* __restrict__ gamma, const float* __restrict__ beta,
                      int N)
{
    __shared__ float sc[32], sh[32];
    if (threadIdx.x < 32) {
        int c = threadIdx.x;
        float inv  = 1.0f / (float)N;
        float mean = stats[c] * inv;
        float var  = stats[32 + c] * inv - mean * mean;
        float sfac = rsqrtf(var + EPS) * gamma[c];
        sc[c] = sfac;
        sh[c] = beta[c] - mean * sfac;
    }
    __syncthreads();

    int i = blockIdx.x * blockDim.x + threadIdx.x;
    int row = i >> 2, tg = i & 3;
    if (row >= N) return;
    uint4 v = __ldg((const uint4*)x + (size_t)row * 4 + tg);
    uint4 o;
#pragma unroll
    for (int qd = 0; qd < 4; ++qd) {
        int c = tg * 2 + qd * 8;
        __half2 h = *(__half2*)(((u32*)&v) + qd);
        float2 f = __half22float2(h);
        float z0 = f.x * sc[c] + sh[c];
        float z1 = f.y * sc[c + 1] + sh[c + 1];
        z0 = (z0 > 0.f) ? z0 : expm1f(z0);
        z1 = (z1 > 0.f) ? z1 : expm1f(z1);
        ((u32*)&o)[qd] = pack_h2(z0, z1);
    }
    ((uint4*)y)[(size_t)row * 4 + tg] = o;
}

// ---------------------------------------------------------------------------
// Final BN + ELU: permuted fp16 in -> logical fp32 out (unpermute folded).
// Thread per (row, tg): word qd holds logical channels (tg*2+qd*8, +1).
// ---------------------------------------------------------------------------
__global__ __launch_bounds__(256)
void bnelu_h2f_kernel(const __half* __restrict__ x, float* __restrict__ y,
                      const float* __restrict__ stats,
                      const float* __restrict__ gamma, const float* __restrict__ beta,
                      int N)
{
    __shared__ float sc[32], sh[32];
    if (threadIdx.x < 32) {
        int c = threadIdx.x;
        float inv  = 1.0f / (float)N;
        float mean = stats[c] * inv;
        float var  = stats[32 + c] * inv - mean * mean;
        float sfac = rsqrtf(var + EPS) * gamma[c];
        sc[c] = sfac;
        sh[c] = beta[c] - mean * sfac;
    }
    __syncthreads();

    int i = blockIdx.x * blockDim.x + threadIdx.x;
    int row = i >> 2, tg = i & 3;
    if (row >= N) return;
    uint4 v = __ldg((const uint4*)x + (size_t)row * 4 + tg);
    float* dst = y + (size_t)row * 32;
#pragma unroll
    for (int qd = 0; qd < 4; ++qd) {
        int c = tg * 2 + qd * 8;
        __half2 h = *(__half2*)(((u32*)&v) + qd);
        float2 f = __half22float2(h);
        float z0 = f.x * sc[c] + sh[c];
        float z1 = f.y * sc[c + 1] + sh[c + 1];
        z0 = (z0 > 0.f) ? z0 : expm1f(z0);
        z1 = (z1 > 0.f) ? z1 : expm1f(z1);
        *(float2*)(dst + c) = make_float2(z0, z1);
    }
}

// ---------------------------------------------------------------------------
extern "C" void kernel_launch(void* const* d_in, const int* in_sizes, int n_in,
                              void* d_out, int out_size)
{
    const float* feats = (const float*)d_in[0];
    const float* W1    = (const float*)d_in[1];
    const float* g1    = (const float*)d_in[2];
    const float* b1    = (const float*)d_in[3];
    const float* W2    = (const float*)d_in[4];
    const float* g2    = (const float*)d_in[5];
    const float* b2    = (const float*)d_in[6];
    const float* W3    = (const float*)d_in[7];
    const float* g3    = (const float*)d_in[8];
    const float* b3    = (const float*)d_in[9];
    const int*   nmap3 = (const int*)d_in[10];
    const int*   nmap2 = (const int*)d_in[11];

    const int N = in_sizes[0] / 32;
    const int ntiles = (N + 255) / 256;
    const int nquads = (N * 4 + 255) / 256;

    __half *hA, *hB;
    float *stats;
    float4* Wp;
    cudaGetSymbolAddress((void**)&hA,    g_hA);
    cudaGetSymbolAddress((void**)&hB,    g_hB);
    cudaGetSymbolAddress((void**)&stats, g_stats);
    cudaGetSymbolAddress((void**)&Wp,    g_Wp);

    prep_weights_all<<<62, 128>>>(W1, W2, W3, Wp);
    cvt_half_kernel<<<nquads, 256>>>(feats, hA, stats, N);

    conv_mma<27><<<ntiles, 256>>>(hA, nmap3, Wp + (size_t)0 * 128, hB, stats + 0, N);
    bnelu_h2h_kernel<<<nquads, 256>>>(hB, hB, stats + 0, g1, b1, N);

    conv_mma<8><<<ntiles, 256>>>(hB, nmap2, Wp + (size_t)27 * 128, hA, stats + 64, N);
    bnelu_h2h_kernel<<<nquads, 256>>>(hA, hA, stats + 64, g2, b2, N);

    conv_mma<27><<<ntiles, 256>>>(hA, nmap3, Wp + (size_t)35 * 128, hB, stats + 128, N);
    bnelu_h2f_kernel<<<nquads, 256>>>(hB, (float*)d_out, stats + 128, g3, b3, N);
}

// round 17
// speedup vs baseline: 1.2775x; 1.0744x over previous
#include <cuda_runtime.h>
#include <cuda_fp16.h>
#include <math.h>
#include <stdint.h>

// ---------------------------------------------------------------------------
// CompletionNet via warp-level fp16 mma.sync (m16n8k16, fp32 accum).
// R17 = R16 (best) with ELU's expm1f replaced by __expf(z)-1 (single MUFU.EX2
// vs ~20-instr expm1 sequence) in all three BN+ELU kernels — they were
// measured issue/ALU-bound (84.9% issue, 16.7% DRAM), not bandwidth-bound.
// Structure: M=32 warp tile, register gather distance-2, idx ring depth 5;
// all convs output permuted fp16; final BN+ELU unpermutes to fp32.
// ---------------------------------------------------------------------------

#define NMAX 500000
#define EPS  1e-5f

__device__ __half g_hA[NMAX * 32];
__device__ __half g_hB[NMAX * 32];
__device__ float  g_stats[3 * 64];
__device__ float4 g_Wp[62 * 128];

typedef unsigned int u32;

__device__ __forceinline__ u32 pack_h2(float lo, float hi) {
    u32 r; asm("cvt.rn.f16x2.f32 %0, %1, %2;" : "=r"(r) : "f"(hi), "f"(lo)); return r;
}
__device__ __forceinline__ float elu_fast(float z) {
    return (z > 0.f) ? z : (__expf(z) - 1.0f);
}

#define MMA_F16(d, a0, a1, a2, a3, b0, b1)                                      \
    asm volatile("mma.sync.aligned.m16n8k16.row.col.f32.f16.f16.f32 "           \
                 "{%0,%1,%2,%3}, {%4,%5,%6,%7}, {%8,%9}, {%0,%1,%2,%3};"        \
                 : "+f"(d[0]), "+f"(d[1]), "+f"(d[2]), "+f"(d[3])               \
                 : "r"(a0), "r"(a1), "r"(a2), "r"(a3), "r"(b0), "r"(b1))

// ---------------------------------------------------------------------------
// Fused weight prep: 62 blocks; 0..26 -> W1, 27..34 -> W2, 35..61 -> W3.
// ---------------------------------------------------------------------------
__global__ void prep_weights_all(const float* __restrict__ W1,
                                 const float* __restrict__ W2,
                                 const float* __restrict__ W3,
                                 float4* __restrict__ dst)
{
    int kb = blockIdx.x;
    const float* W;
    int k;
    if (kb < 27)      { W = W1; k = kb; }
    else if (kb < 35) { W = W2; k = kb - 27; }
    else              { W = W3; k = kb - 35; }

    int t = threadIdx.x;                 // 0..127
    int lane = t & 31, ntp = (t >> 5) & 1, kc = t >> 6;
    int r  = lane >> 2;
    int cL = (lane & 3) * 2;
    int co0 = (2 * ntp) * 8 + r;
    int co1 = co0 + 8;
    const float* Wk = W + k * 1024 + kc * 16 * 32;
    u32 p0 = pack_h2(Wk[(cL + 0) * 32 + co0], Wk[(cL + 1) * 32 + co0]);
    u32 p1 = pack_h2(Wk[(cL + 8) * 32 + co0], Wk[(cL + 9) * 32 + co0]);
    u32 p2 = pack_h2(Wk[(cL + 0) * 32 + co1], Wk[(cL + 1) * 32 + co1]);
    u32 p3 = pack_h2(Wk[(cL + 8) * 32 + co1], Wk[(cL + 9) * 32 + co1]);
    float4 v;
    v.x = __uint_as_float(p0); v.y = __uint_as_float(p1);
    v.z = __uint_as_float(p2); v.w = __uint_as_float(p3);
    dst[kb * 128 + kc * 64 + ntp * 32 + lane] = v;
}

// ---------------------------------------------------------------------------
// feats fp32 -> permuted fp16; block 0 also zeroes the stats buffer.
// ---------------------------------------------------------------------------
__global__ __launch_bounds__(256)
void cvt_half_kernel(const float* __restrict__ x, __half* __restrict__ y,
                     float* __restrict__ stats, int N)
{
    if (blockIdx.x == 0 && threadIdx.x < 192) stats[threadIdx.x] = 0.f;
    int i = blockIdx.x * blockDim.x + threadIdx.x;
    int row = i >> 2, tg = i & 3;
    if (row >= N) return;
    const float2* src = (const float2*)(x + (size_t)row * 32);
    float2 v0 = __ldg(src + tg);
    float2 v1 = __ldg(src + tg + 4);
    float2 v2 = __ldg(src + tg + 8);
    float2 v3 = __ldg(src + tg + 12);
    uint4 o;
    o.x = pack_h2(v0.x, v0.y);
    o.y = pack_h2(v1.x, v1.y);
    o.z = pack_h2(v2.x, v2.y);
    o.w = pack_h2(v3.x, v3.y);
    ((uint4*)y)[(size_t)row * 4 + tg] = o;
}

// ---------------------------------------------------------------------------
__device__ __forceinline__ void gather4(uint4& a, uint4& b, uint4& c, uint4& d,
                                        const __half* __restrict__ in,
                                        int idx, int gid, int tg)
{
    const int iA = __shfl_sync(0xffffffffu, idx, gid);
    const int iB = __shfl_sync(0xffffffffu, idx, 8 + gid);
    const int iC = __shfl_sync(0xffffffffu, idx, 16 + gid);
    const int iD = __shfl_sync(0xffffffffu, idx, 24 + gid);
    a = make_uint4(0u, 0u, 0u, 0u); b = a; c = a; d = a;
    if (iA >= 0) a = __ldg((const uint4*)(in + (size_t)iA * 32) + tg);
    if (iB >= 0) b = __ldg((const uint4*)(in + (size_t)iB * 32) + tg);
    if (iC >= 0) c = __ldg((const uint4*)(in + (size_t)iC * 32) + tg);
    if (iD >= 0) d = __ldg((const uint4*)(in + (size_t)iD * 32) + tg);
}

// ---------------------------------------------------------------------------
// conv: block = 256 threads (8 warps), tile = 256 voxels x 32 out-channels.
// Warp tile M=32, gather distance-2, idx ring depth 5.
// Output: permuted fp16 (one uint4 per row-quarter). BN stats fused (fp32).
// ---------------------------------------------------------------------------
template<int KVOL>
__global__ __launch_bounds__(256, 2)
void conv_mma(const __half* __restrict__ in, const int* __restrict__ nmap,
              const float4* __restrict__ Wp, __half* __restrict__ out,
              float* __restrict__ stats, int N)
{
    __shared__ float Red[8 * 64];

    const int tid  = threadIdx.x;
    const int wid  = tid >> 5, lane = tid & 31;
    const int gid  = lane >> 2, tg = lane & 3;
    const int mbase = blockIdx.x * 256;
    const int mrow  = mbase + wid * 32 + lane;
    const bool mv   = (mrow < N);

    float acc[2][4][4];
#pragma unroll
    for (int mt = 0; mt < 2; ++mt)
#pragma unroll
        for (int nt = 0; nt < 4; ++nt)
#pragma unroll
            for (int j = 0; j < 4; ++j) acc[mt][nt][j] = 0.f;

    // ---- idx ring: depth 5 ----
    int idxr[5];
#pragma unroll
    for (int j = 0; j < 5; ++j)
        idxr[j] = (j < KVOL && mv) ? __ldg(nmap + (size_t)j * N + mrow) : -1;

    // ---- prime 2 gather stages ----
    uint4 cA, cB, cC, cD;
    gather4(cA, cB, cC, cD, in, idxr[0], gid, tg);
    uint4 nA = make_uint4(0,0,0,0), nB = nA, nC = nA, nD = nA;
    if (KVOL > 1) gather4(nA, nB, nC, nD, in, idxr[1], gid, tg);

#pragma unroll
    for (int k = 0; k < KVOL; ++k) {
        uint4 pA = make_uint4(0,0,0,0), pB = pA, pC = pA, pD = pA;
        if (k + 2 < KVOL) gather4(pA, pB, pC, pD, in, idxr[(k + 2) % 5], gid, tg);
        idxr[k % 5] = (k + 5 < KVOL && mv)
                    ? __ldg(nmap + (size_t)(k + 5) * N + mrow) : -1;

        const float4* wb = Wp + (size_t)k * 128 + lane;
#pragma unroll
        for (int ntp = 0; ntp < 2; ++ntp) {
            float4 w0 = __ldg(wb + ntp * 32);          // kc = 0
            float4 w1 = __ldg(wb + 64 + ntp * 32);     // kc = 1
            const u32 b00 = __float_as_uint(w0.x), b01 = __float_as_uint(w0.y);
            const u32 b02 = __float_as_uint(w0.z), b03 = __float_as_uint(w0.w);
            const u32 b10 = __float_as_uint(w1.x), b11 = __float_as_uint(w1.y);
            const u32 b12 = __float_as_uint(w1.z), b13 = __float_as_uint(w1.w);
            MMA_F16(acc[0][2 * ntp + 0], cA.x, cB.x, cA.y, cB.y, b00, b01);
            MMA_F16(acc[0][2 * ntp + 1], cA.x, cB.x, cA.y, cB.y, b02, b03);
            MMA_F16(acc[0][2 * ntp + 0], cA.z, cB.z, cA.w, cB.w, b10, b11);
            MMA_F16(acc[0][2 * ntp + 1], cA.z, cB.z, cA.w, cB.w, b12, b13);
            MMA_F16(acc[1][2 * ntp + 0], cC.x, cD.x, cC.y, cD.y, b00, b01);
            MMA_F16(acc[1][2 * ntp + 1], cC.x, cD.x, cC.y, cD.y, b02, b03);
            MMA_F16(acc[1][2 * ntp + 0], cC.z, cD.z, cC.w, cD.w, b10, b11);
            MMA_F16(acc[1][2 * ntp + 1], cC.z, cD.z, cC.w, cD.w, b12, b13);
        }
        cA = nA; cB = nB; cC = nC; cD = nD;
        nA = pA; nB = pB; nC = pC; nD = pD;
    }

    // ---- epilogue: permuted fp16 store + fused BN stats (fp32 accum) ----
#pragma unroll
    for (int mt = 0; mt < 2; ++mt) {
        const int r0 = mbase + wid * 32 + mt * 16 + gid;
        const int r1 = r0 + 8;
        uint4 o0, o1;
        o0.x = pack_h2(acc[mt][0][0], acc[mt][0][1]);
        o0.y = pack_h2(acc[mt][1][0], acc[mt][1][1]);
        o0.z = pack_h2(acc[mt][2][0], acc[mt][2][1]);
        o0.w = pack_h2(acc[mt][3][0], acc[mt][3][1]);
        o1.x = pack_h2(acc[mt][0][2], acc[mt][0][3]);
        o1.y = pack_h2(acc[mt][1][2], acc[mt][1][3]);
        o1.z = pack_h2(acc[mt][2][2], acc[mt][2][3]);
        o1.w = pack_h2(acc[mt][3][2], acc[mt][3][3]);
        if (r0 < N) ((uint4*)out)[(size_t)r0 * 4 + tg] = o0;
        if (r1 < N) ((uint4*)out)[(size_t)r1 * 4 + tg] = o1;
    }

    float s[4][2], q[4][2];
#pragma unroll
    for (int nt = 0; nt < 4; ++nt)
#pragma unroll
        for (int j = 0; j < 2; ++j) {
            float v0 = acc[0][nt][j], v1 = acc[0][nt][2 + j];
            float v2 = acc[1][nt][j], v3 = acc[1][nt][2 + j];
            s[nt][j] = (v0 + v1) + (v2 + v3);
            q[nt][j] = (v0 * v0 + v1 * v1) + (v2 * v2 + v3 * v3);
        }
#pragma unroll
    for (int off = 4; off < 32; off <<= 1)
#pragma unroll
        for (int nt = 0; nt < 4; ++nt)
#pragma unroll
            for (int j = 0; j < 2; ++j) {
                s[nt][j] += __shfl_xor_sync(0xffffffffu, s[nt][j], off);
                q[nt][j] += __shfl_xor_sync(0xffffffffu, q[nt][j], off);
            }
    if (lane < 4) {
#pragma unroll
        for (int nt = 0; nt < 4; ++nt)
#pragma unroll
            for (int j = 0; j < 2; ++j) {
                int c = nt * 8 + tg * 2 + j;
                Red[wid * 64 + c]      = s[nt][j];
                Red[wid * 64 + 32 + c] = q[nt][j];
            }
    }
    __syncthreads();
    if (tid < 64) {
        int plane = tid >> 5, c = tid & 31;
        float v = 0.f;
#pragma unroll
        for (int i = 0; i < 8; ++i) v += Red[i * 64 + plane * 32 + c];
        atomicAdd(stats + plane * 32 + c, v);
    }
}

// ---------------------------------------------------------------------------
// BN + ELU on permuted fp16 in -> permuted fp16 out. Thread per (row, tg).
// ---------------------------------------------------------------------------
__global__ __launch_bounds__(256)
void bnelu_h2h_kernel(const __half* __restrict__ x, __half* __restrict__ y,
                      const float* __restrict__ stats,
                      const float* __restrict__ gamma, const float* __restrict__ beta,
                      int N)
{
    __shared__ float sc[32], sh[32];
    if (threadIdx.x < 32) {
        int c = threadIdx.x;
        float inv  = 1.0f / (float)N;
        float mean = stats[c] * inv;
        float var  = stats[32 + c] * inv - mean * mean;
        float sfac = rsqrtf(var + EPS) * gamma[c];
        sc[c] = sfac;
        sh[c] = beta[c] - mean * sfac;
    }
    __syncthreads();

    int i = blockIdx.x * blockDim.x + threadIdx.x;
    int row = i >> 2, tg = i & 3;
    if (row >= N) return;
    uint4 v = __ldg((const uint4*)x + (size_t)row * 4 + tg);
    uint4 o;
#pragma unroll
    for (int qd = 0; qd < 4; ++qd) {
        int c = tg * 2 + qd * 8;
        __half2 h = *(__half2*)(((u32*)&v) + qd);
        float2 f = __half22float2(h);
        float z0 = elu_fast(fmaf(f.x, sc[c],     sh[c]));
        float z1 = elu_fast(fmaf(f.y, sc[c + 1], sh[c + 1]));
        ((u32*)&o)[qd] = pack_h2(z0, z1);
    }
    ((uint4*)y)[(size_t)row * 4 + tg] = o;
}

// ---------------------------------------------------------------------------
// Final BN + ELU: permuted fp16 in -> logical fp32 out (unpermute folded).
// ---------------------------------------------------------------------------
__global__ __launch_bounds__(256)
void bnelu_h2f_kernel(const __half* __restrict__ x, float* __restrict__ y,
                      const float* __restrict__ stats,
                      const float* __restrict__ gamma, const float* __restrict__ beta,
                      int N)
{
    __shared__ float sc[32], sh[32];
    if (threadIdx.x < 32) {
        int c = threadIdx.x;
        float inv  = 1.0f / (float)N;
        float mean = stats[c] * inv;
        float var  = stats[32 + c] * inv - mean * mean;
        float sfac = rsqrtf(var + EPS) * gamma[c];
        sc[c] = sfac;
        sh[c] = beta[c] - mean * sfac;
    }
    __syncthreads();

    int i = blockIdx.x * blockDim.x + threadIdx.x;
    int row = i >> 2, tg = i & 3;
    if (row >= N) return;
    uint4 v = __ldg((const uint4*)x + (size_t)row * 4 + tg);
    float* dst = y + (size_t)row * 32;
#pragma unroll
    for (int qd = 0; qd < 4; ++qd) {
        int c = tg * 2 + qd * 8;
        __half2 h = *(__half2*)(((u32*)&v) + qd);
        float2 f = __half22float2(h);
        float z0 = elu_fast(fmaf(f.x, sc[c],     sh[c]));
        float z1 = elu_fast(fmaf(f.y, sc[c + 1], sh[c + 1]));
        *(float2*)(dst + c) = make_float2(z0, z1);
    }
}

// ---------------------------------------------------------------------------
extern "C" void kernel_launch(void* const* d_in, const int* in_sizes, int n_in,
                              void* d_out, int out_size)
{
    const float* feats = (const float*)d_in[0];
    const float* W1    = (const float*)d_in[1];
    const float* g1    = (const float*)d_in[2];
    const float* b1    = (const float*)d_in[3];
    const float* W2    = (const float*)d_in[4];
    const float* g2    = (const float*)d_in[5];
    const float* b2    = (const float*)d_in[6];
    const float* W3    = (const float*)d_in[7];
    const float* g3    = (const float*)d_in[8];
    const float* b3    = (const float*)d_in[9];
    const int*   nmap3 = (const int*)d_in[10];
    const int*   nmap2 = (const int*)d_in[11];

    const int N = in_sizes[0] / 32;
    const int ntiles = (N + 255) / 256;
    const int nquads = (N * 4 + 255) / 256;

    __half *hA, *hB;
    float *stats;
    float4* Wp;
    cudaGetSymbolAddress((void**)&hA,    g_hA);
    cudaGetSymbolAddress((void**)&hB,    g_hB);
    cudaGetSymbolAddress((void**)&stats, g_stats);
    cudaGetSymbolAddress((void**)&Wp,    g_Wp);

    prep_weights_all<<<62, 128>>>(W1, W2, W3, Wp);
    cvt_half_kernel<<<nquads, 256>>>(feats, hA, stats, N);

    conv_mma<27><<<ntiles, 256>>>(hA, nmap3, Wp + (size_t)0 * 128, hB, stats + 0, N);
    bnelu_h2h_kernel<<<nquads, 256>>>(hB, hB, stats + 0, g1, b1, N);

    conv_mma<8><<<ntiles, 256>>>(hB, nmap2, Wp + (size_t)27 * 128, hA, stats + 64, N);
    bnelu_h2h_kernel<<<nquads, 256>>>(hA, hA, stats + 64, g2, b2, N);

    conv_mma<27><<<ntiles, 256>>>(hA, nmap3, Wp + (size_t)35 * 128, hB, stats + 128, N);
    bnelu_h2f_kernel<<<nquads, 256>>>(hB, (float*)d_out, stats + 128, g3, b3, N);
}